// round 14
// baseline (speedup 1.0000x reference)
#include <cuda_runtime.h>
#include <cuda_bf16.h>
#include <math.h>
#include <stdint.h>

#define Bv 8
#define Cv 256
#define NW 1024      // 32*32 super tokens
#define NHEADS 8
#define HD 32

// ---------------- scratch (static device memory; no allocs) ----------------
__device__ float g_wf[Bv * NW * Cv];                 // (b, t, c)
__device__ float g_aff[Bv * NW * 16 * 9];            // (b, t, p, i)
__device__ float g_wf2raw[(size_t)Bv * NW * 9 * Cv]; // (b, t, i, c)
__device__ float g_affsumraw[Bv * NW * 9];           // (b, t, i)
__device__ __nv_bfloat16 g_wf2h[Bv * NW * Cv];       // tokens hi (b, t, c)
__device__ __nv_bfloat16 g_wf2l[Bv * NW * Cv];       // tokens lo
__device__ __nv_bfloat16 g_qkvwh[768 * 256];         // qkv weight hi (o,k)
__device__ __nv_bfloat16 g_qkvwl[768 * 256];
__device__ __nv_bfloat16 g_pwh[256 * 256];           // proj weight hi (o,k)
__device__ __nv_bfloat16 g_pwl[256 * 256];
__device__ __nv_bfloat16 g_qkh[(size_t)Bv * NW * 768];  // qkv out hi (b, n, o)
__device__ __nv_bfloat16 g_qkl[(size_t)Bv * NW * 768];  // qkv out lo
__device__ unsigned short g_vTh[(size_t)Bv * 8 * 32 * 1024]; // V^T hi (b,h,d,n)
__device__ unsigned short g_vTl[(size_t)Bv * 8 * 32 * 1024]; // V^T lo
__device__ __nv_bfloat16 g_aoh[Bv * NW * Cv];        // attn out hi (b, n, c)
__device__ __nv_bfloat16 g_aol[Bv * NW * Cv];        // attn out lo
__device__ float g_proj[(size_t)Bv * NW * Cv];       // (b, n, o)

// ---------------- f32x2 packed-math helpers (sm_103a) ----------------
typedef unsigned long long u64;
__device__ __forceinline__ u64 f2_dup(float a) {
    u64 d; asm("mov.b64 %0, {%1, %1};" : "=l"(d) : "f"(a)); return d;
}
__device__ __forceinline__ void f2_unpack(float& a, float& b, u64 d) {
    asm("mov.b64 {%0, %1}, %2;" : "=f"(a), "=f"(b) : "l"(d));
}
__device__ __forceinline__ void fma2(u64& c, u64 a, u64 b) {
    asm("fma.rn.f32x2 %0, %1, %2, %0;" : "+l"(c) : "l"(a), "l"(b));
}
__device__ __forceinline__ u64 lds64(unsigned saddr) {
    u64 v;
    asm volatile("ld.shared.b64 %0, [%1];" : "=l"(v) : "r"(saddr));
    return v;
}
__device__ __forceinline__ unsigned lds32(unsigned saddr) {
    unsigned v;
    asm volatile("ld.shared.b32 %0, [%1];" : "=r"(v) : "r"(saddr));
    return v;
}
__device__ __forceinline__ unsigned smem_u32(const void* p) {
    unsigned a;
    asm("{ .reg .u64 t; cvta.to.shared.u64 t, %1; cvt.u32.u64 %0, t; }" : "=r"(a) : "l"(p));
    return a;
}
// pack: low half = lo, high half = hi (PTX: first src -> upper)
__device__ __forceinline__ unsigned pack_bf16x2(float lo, float hi) {
    unsigned d;
    asm("cvt.rn.bf16x2.f32 %0, %1, %2;" : "=r"(d) : "f"(hi), "f"(lo));
    return d;
}

// ---------------- mma.sync + cp.async helpers (portable sm_80+) -------------
__device__ __forceinline__ void mma16816(float* c, const unsigned* a, const unsigned* b) {
    asm volatile(
        "mma.sync.aligned.m16n8k16.row.col.f32.bf16.bf16.f32 "
        "{%0,%1,%2,%3}, {%4,%5,%6,%7}, {%8,%9}, {%0,%1,%2,%3};"
        : "+f"(c[0]), "+f"(c[1]), "+f"(c[2]), "+f"(c[3])
        : "r"(a[0]), "r"(a[1]), "r"(a[2]), "r"(a[3]), "r"(b[0]), "r"(b[1]));
}
#define CPA16(dst, src) \
    asm volatile("cp.async.ca.shared.global [%0], [%1], 16;" :: "r"(dst), "l"(src))
#define CPA_COMMIT() asm volatile("cp.async.commit_group;" ::: "memory")
#define CPA_WAIT(n)  asm volatile("cp.async.wait_group %0;" :: "n"(n) : "memory")

// ---------------- kernel 1: 4x4 average pool -> wf (float4) ----------------
__global__ void pool_kernel(const float* __restrict__ x) {
    int b = blockIdx.y;
    int t = blockIdx.x * 4 + (threadIdx.x >> 6);
    int c4 = (threadIdx.x & 63) * 4;
    int Y = t >> 5, X = t & 31;
    const float* xb = x + (size_t)b * 16384 * 256;
    float4 s = make_float4(0.f, 0.f, 0.f, 0.f);
#pragma unroll
    for (int py = 0; py < 4; py++)
#pragma unroll
        for (int px = 0; px < 4; px++) {
            int n = (Y * 4 + py) * 128 + X * 4 + px;
            float4 v = *(const float4*)&xb[(size_t)n * 256 + c4];
            s.x += v.x; s.y += v.y; s.z += v.z; s.w += v.w;
        }
    s.x *= (1.f / 16.f); s.y *= (1.f / 16.f); s.z *= (1.f / 16.f); s.w *= (1.f / 16.f);
    *(float4*)&g_wf[((size_t)b * NW + t) * Cv + c4] = s;
}

// ---------------- weight conversion: fp32 -> bf16 hi/lo (both weights) ------
__global__ void conv_w(const float* __restrict__ qw, const float* __restrict__ pw) {
    int i = blockIdx.x * 256 + threadIdx.x;
    if (i < 768 * 256) {
        float x = qw[i];
        __nv_bfloat16 h = __float2bfloat16(x);
        g_qkvwh[i] = h;
        g_qkvwl[i] = __float2bfloat16(x - __bfloat162float(h));
    }
    if (i < 256 * 256) {
        float x = pw[i];
        __nv_bfloat16 h = __float2bfloat16(x);
        g_pwh[i] = h;
        g_pwl[i] = __float2bfloat16(x - __bfloat162float(h));
    }
}

// ---------------- kernel 2: affinity softmax + wf2 window partials ----------
// Dot phase: warp owns 2 p-rows; pix register-cached; paired-half reduction.
__global__ void aff_kernel(const float* __restrict__ x) {
    __shared__ float pix[16][256];
    __shared__ float wfu[9][256];
    __shared__ float lg[16][9];
    __shared__ float affs[16][9];
    int b = blockIdx.y, t = blockIdx.x, tid = threadIdx.x;
    int Y = t >> 5, X = t & 31;
    const float* xb = x + (size_t)b * 16384 * 256;
    {
        int c4 = (tid & 63) * 4;
#pragma unroll
        for (int pp = 0; pp < 4; pp++) {
            int p = pp * 4 + (tid >> 6);
            int n = (Y * 4 + (p >> 2)) * 128 + X * 4 + (p & 3);
            *(float4*)&pix[p][c4] = *(const float4*)&xb[(size_t)n * 256 + c4];
        }
#pragma unroll
        for (int ii = 0; ii < 3; ii++) {
            int i = ii * 4 + (tid >> 6);
            if (i < 9) {
                int ny = Y + (i / 3) - 1, nx = X + (i % 3) - 1;
                float4 v = make_float4(0.f, 0.f, 0.f, 0.f);
                if ((unsigned)ny < 32u && (unsigned)nx < 32u)
                    v = *(const float4*)&g_wf[((size_t)b * NW + ny * 32 + nx) * Cv + c4];
                *(float4*)&wfu[i][c4] = v;
            }
        }
    }
    __syncthreads();
    int warp = tid >> 5, lane = tid & 31;
    {
        int p0 = warp * 2, p1 = p0 + 1;
        unsigned pixb = smem_u32(&pix[0][0]) + (unsigned)lane * 8 + (unsigned)p0 * 1024;
        unsigned wfub = smem_u32(&wfu[0][0]) + (unsigned)lane * 8;
        u64 pr0[4], pr1[4];
#pragma unroll
        for (int k = 0; k < 4; k++) {
            pr0[k] = lds64(pixb + k * 256);
            pr1[k] = lds64(pixb + 1024 + k * 256);
        }
#pragma unroll
        for (int i = 0; i < 9; i++) {
            u64 s0 = 0ull, s1 = 0ull;
#pragma unroll
            for (int k = 0; k < 4; k++) {
                u64 wf = lds64(wfub + i * 1024 + k * 256);
                fma2(s0, pr0[k], wf);
                fma2(s1, pr1[k], wf);
            }
            float a0, c0, a1, c1;
            f2_unpack(a0, c0, s0);
            f2_unpack(a1, c1, s1);
            float v0 = a0 + c0, v1 = a1 + c1;
            float td = __shfl_down_sync(0xffffffffu, v0, 16);
            float tu = __shfl_up_sync(0xffffffffu, v1, 16);
            float wv = (lane < 16) ? (v0 + td) : (v1 + tu);
#pragma unroll
            for (int off = 8; off; off >>= 1)
                wv += __shfl_down_sync(0xffffffffu, wv, off);
            if (lane == 0)  lg[p0][i] = wv * 0.0625f;
            if (lane == 16) lg[p1][i] = wv * 0.0625f;
        }
    }
    __syncthreads();
    if (tid < 16) {
        float m = -1e30f;
#pragma unroll
        for (int i = 0; i < 9; i++) m = fmaxf(m, lg[tid][i]);
        float e[9], sum = 0.f;
#pragma unroll
        for (int i = 0; i < 9; i++) { e[i] = __expf(lg[tid][i] - m); sum += e[i]; }
        float inv = 1.f / sum;
#pragma unroll
        for (int i = 0; i < 9; i++) affs[tid][i] = e[i] * inv;
    }
    __syncthreads();
    if (tid < 144)
        g_aff[((size_t)b * NW + t) * 144 + tid] = affs[tid / 9][tid % 9];
    if (tid >= 160 && tid < 169) {
        int i = tid - 160;
        float s = 0.f;
#pragma unroll
        for (int p = 0; p < 16; p++) s += affs[p][i];
        g_affsumraw[((size_t)b * NW + t) * 9 + i] = s;
    }
    float acc[9];
#pragma unroll
    for (int i = 0; i < 9; i++) acc[i] = 0.f;
#pragma unroll
    for (int p = 0; p < 16; p++) {
        float v = pix[p][tid];
#pragma unroll
        for (int i = 0; i < 9; i++) acc[i] = fmaf(v, affs[p][i], acc[i]);
    }
    size_t base = ((size_t)b * NW + t) * 9 * Cv;
#pragma unroll
    for (int i = 0; i < 9; i++) g_wf2raw[base + (size_t)i * Cv + tid] = acc[i];
}

// ---------------- kernel 3: fold-gather + normalize -> bf16 hi/lo -----------
// asum inverses staged in smem (36 loads/block vs 2304); uint2 pair stores.
__global__ void fold_kernel() {
    __shared__ float s_inv[4];
    int b = blockIdx.y;
    int tl = threadIdx.x >> 6;
    int t = blockIdx.x * 4 + tl;
    int c = (threadIdx.x & 63) * 4;
    int Y = t >> 5, X = t & 31;
    if (threadIdx.x < 4) {
        int tt = blockIdx.x * 4 + threadIdx.x;
        int Yt = tt >> 5, Xt = tt & 31;
        float asum = 0.f;
#pragma unroll
        for (int i = 0; i < 9; i++) {
            int ny = Yt - ((i / 3) - 1), nx = Xt - ((i % 3) - 1);
            if ((unsigned)ny < 32u && (unsigned)nx < 32u)
                asum += g_affsumraw[((size_t)b * NW + ny * 32 + nx) * 9 + i];
        }
        s_inv[threadIdx.x] = 1.f / (asum + 1e-12f);
    }
    __syncthreads();
    float4 acc = make_float4(0.f, 0.f, 0.f, 0.f);
#pragma unroll
    for (int i = 0; i < 9; i++) {
        int ny = Y - ((i / 3) - 1), nx = X - ((i % 3) - 1);
        if ((unsigned)ny < 32u && (unsigned)nx < 32u) {
            size_t nb = (size_t)b * NW + ny * 32 + nx;
            float4 v = *(const float4*)&g_wf2raw[(nb * 9 + i) * Cv + c];
            acc.x += v.x; acc.y += v.y; acc.z += v.z; acc.w += v.w;
        }
    }
    float inv = s_inv[tl];
    float f[4] = {acc.x * inv, acc.y * inv, acc.z * inv, acc.w * inv};
    size_t off = ((size_t)b * NW + t) * Cv + c;
    unsigned h01 = pack_bf16x2(f[0], f[1]);
    unsigned h23 = pack_bf16x2(f[2], f[3]);
    unsigned l01 = pack_bf16x2(f[0] - __uint_as_float(h01 << 16),
                               f[1] - __uint_as_float(h01 & 0xffff0000u));
    unsigned l23 = pack_bf16x2(f[2] - __uint_as_float(h23 << 16),
                               f[3] - __uint_as_float(h23 & 0xffff0000u));
    *(uint2*)&g_wf2h[off] = make_uint2(h01, h23);
    *(uint2*)&g_wf2l[off] = make_uint2(l01, l23);
}

// ---------------- GEMM via mma.sync bf16 (3-term hi/lo split) ---------------
// which==0 (qkv): coalesced qk + V^T writes via smem-transposed staging.
// which==1 (proj): f32+bias.
#define STG_STRIDE 40960
__global__ void __launch_bounds__(256) gemm_mma(int which,
                                                const float* __restrict__ bias,
                                                int outStride) {
    extern __shared__ __align__(16) char sm[];
    int b = blockIdx.z;
    int n0 = blockIdx.x * 128, o0 = blockIdx.y * 128;
    int tid = threadIdx.x;
    int w = tid >> 5, lane = tid & 31, g = lane >> 2, t = lane & 3;
    int wm = (w >> 2) * 64, wn = (w & 3) * 32;

    const __nv_bfloat16* Ah = (which == 0 ? g_wf2h : g_aoh) + (size_t)b * NW * Cv;
    const __nv_bfloat16* Al = (which == 0 ? g_wf2l : g_aol) + (size_t)b * NW * Cv;
    const __nv_bfloat16* Bh = (which == 0 ? g_qkvwh : g_pwh);
    const __nv_bfloat16* Bl = (which == 0 ? g_qkvwl : g_pwl);

    unsigned smb = smem_u32(sm);
    int lr0 = tid >> 2, lq = tid & 3;
    int lr1 = lr0 + 64;
    unsigned sd0 = lr0 * 80 + lq * 16;
    unsigned sd1 = lr1 * 80 + lq * 16;

    float acc[4][4][4];
#pragma unroll
    for (int mt = 0; mt < 4; mt++)
#pragma unroll
        for (int nt = 0; nt < 4; nt++)
#pragma unroll
            for (int j = 0; j < 4; j++) acc[mt][nt][j] = 0.f;

#define ISSUE_CHUNK(kc, s) do {                                                \
    unsigned sb = smb + (s) * STG_STRIDE;                                      \
    size_t ga0 = (size_t)(n0 + lr0) * 256 + (kc) * 32 + lq * 8;                \
    size_t ga1 = (size_t)(n0 + lr1) * 256 + (kc) * 32 + lq * 8;                \
    size_t gb0 = (size_t)(o0 + lr0) * 256 + (kc) * 32 + lq * 8;                \
    size_t gb1 = (size_t)(o0 + lr1) * 256 + (kc) * 32 + lq * 8;                \
    CPA16(sb + sd0,         Ah + ga0);  CPA16(sb + sd1,         Ah + ga1);     \
    CPA16(sb + 10240 + sd0, Al + ga0);  CPA16(sb + 10240 + sd1, Al + ga1);     \
    CPA16(sb + 20480 + sd0, Bh + gb0);  CPA16(sb + 20480 + sd1, Bh + gb1);     \
    CPA16(sb + 30720 + sd0, Bl + gb0);  CPA16(sb + 30720 + sd1, Bl + gb1);     \
    CPA_COMMIT();                                                              \
} while (0)

    ISSUE_CHUNK(0, 0);
    ISSUE_CHUNK(1, 1);
#pragma unroll 1
    for (int c = 0; c < 8; c++) {
        if (c < 7) { CPA_WAIT(1); } else { CPA_WAIT(0); }
        __syncthreads();
        unsigned stage = smb + (c & 1) * STG_STRIDE;
#pragma unroll
        for (int ks = 0; ks < 2; ks++) {
            unsigned kb = ks * 32;
            unsigned bhf[4][2], blf[4][2];
#pragma unroll
            for (int nt = 0; nt < 4; nt++) {
                unsigned ba = stage + 20480 + (unsigned)(wn + nt * 8 + g) * 80 + t * 4 + kb;
                bhf[nt][0] = lds32(ba);          bhf[nt][1] = lds32(ba + 16);
                blf[nt][0] = lds32(ba + 10240);  blf[nt][1] = lds32(ba + 10256);
            }
#pragma unroll
            for (int mt = 0; mt < 4; mt++) {
                unsigned aa = stage + (unsigned)(wm + mt * 16 + g) * 80 + t * 4 + kb;
                unsigned ahf[4], alf[4];
                ahf[0] = lds32(aa);        ahf[1] = lds32(aa + 640);
                ahf[2] = lds32(aa + 16);   ahf[3] = lds32(aa + 656);
                alf[0] = lds32(aa + 10240);        alf[1] = lds32(aa + 10880);
                alf[2] = lds32(aa + 10256);        alf[3] = lds32(aa + 10896);
#pragma unroll
                for (int nt = 0; nt < 4; nt++) {
                    mma16816(acc[mt][nt], ahf, bhf[nt]);
                    mma16816(acc[mt][nt], ahf, blf[nt]);
                    mma16816(acc[mt][nt], alf, bhf[nt]);
                }
            }
        }
        __syncthreads();
        if (c < 6) ISSUE_CHUNK(c + 2, c & 1);
    }
#undef ISSUE_CHUNK

    if (which == 1) {
#pragma unroll
        for (int nt = 0; nt < 4; nt++) {
            int col = o0 + wn + nt * 8 + t * 2;
            float b0 = __ldg(&bias[col]), b1 = __ldg(&bias[col + 1]);
#pragma unroll
            for (int mt = 0; mt < 4; mt++) {
                int row = n0 + wm + mt * 16 + g;
                float* p = g_proj + ((size_t)b * NW + row) * 256 + col;
                *(float2*)p = make_float2(acc[mt][nt][0] + b0, acc[mt][nt][1] + b1);
                *(float2*)(p + (size_t)8 * 256) =
                    make_float2(acc[mt][nt][2] + b0, acc[mt][nt][3] + b1);
            }
        }
    } else {
        // stage full 128x128 block transposed in smem (pitch 136 ushort)
        unsigned short* vtb_h = (unsigned short*)sm;            // [128][136]
        unsigned short* vtb_l = (unsigned short*)(sm + 34816);  // [128][136]
#pragma unroll
        for (int nt = 0; nt < 4; nt++) {
            int colL = wn + nt * 8 + t * 2;
#pragma unroll
            for (int mt = 0; mt < 4; mt++) {
#pragma unroll
                for (int rr = 0; rr < 2; rr++) {
                    int rl = wm + mt * 16 + g + rr * 8;
                    float v0 = acc[mt][nt][rr * 2], v1 = acc[mt][nt][rr * 2 + 1];
                    unsigned hpair = pack_bf16x2(v0, v1);
                    float h0f = __uint_as_float(hpair << 16);
                    float h1f = __uint_as_float(hpair & 0xffff0000u);
                    unsigned lpair = pack_bf16x2(v0 - h0f, v1 - h1f);
                    vtb_h[colL * 136 + rl] = (unsigned short)(hpair & 0xffffu);
                    vtb_h[(colL + 1) * 136 + rl] = (unsigned short)(hpair >> 16);
                    vtb_l[colL * 136 + rl] = (unsigned short)(lpair & 0xffffu);
                    vtb_l[(colL + 1) * 136 + rl] = (unsigned short)(lpair >> 16);
                }
            }
        }
        __syncthreads();
        // coalesced token-major qk writes (16B per thread-iter)
#pragma unroll
        for (int it = 0; it < 8; it++) {
            int idx = tid + it * 256;
            int row = idx >> 4, seg = idx & 15;
            unsigned hv[4], lv[4];
#pragma unroll
            for (int j = 0; j < 4; j++) {
                unsigned short h0 = vtb_h[(seg * 8 + 2 * j) * 136 + row];
                unsigned short h1 = vtb_h[(seg * 8 + 2 * j + 1) * 136 + row];
                unsigned short l0 = vtb_l[(seg * 8 + 2 * j) * 136 + row];
                unsigned short l1 = vtb_l[(seg * 8 + 2 * j + 1) * 136 + row];
                hv[j] = (unsigned)h0 | ((unsigned)h1 << 16);
                lv[j] = (unsigned)l0 | ((unsigned)l1 << 16);
            }
            size_t oo = ((size_t)b * NW + n0 + row) * 768 + o0 + seg * 8;
            *(uint4*)&g_qkh[oo] = make_uint4(hv[0], hv[1], hv[2], hv[3]);
            *(uint4*)&g_qkl[oo] = make_uint4(lv[0], lv[1], lv[2], lv[3]);
        }
        // coalesced V^T writes: rows that are V columns (col%96 >= 64)
#pragma unroll
        for (int it = 0; it < 8; it++) {
            int idx = tid + it * 256;
            int row = idx >> 4, seg = idx & 15;
            int col = o0 + row;
            int cm = col % 96, hh = col / 96;
            if (cm >= 64) {
                size_t vb = (((size_t)b * 8 + hh) * 32 + (cm - 64)) * 1024 + n0 + seg * 8;
                *(uint4*)&g_vTh[vb] = *(uint4*)&vtb_h[row * 136 + seg * 8];
                *(uint4*)&g_vTl[vb] = *(uint4*)&vtb_l[row * 136 + seg * 8];
            }
        }
    }
}

// ---------------- kernel 5: flash-MMA attention, cp.async double-buffered ---
#define ATT_STAGE 42240
#define ATT_SMEM (20480 + 2 * ATT_STAGE)
__global__ void __launch_bounds__(256) attn_mma() {
    extern __shared__ __align__(16) char asm_[];
    int qb = blockIdx.x, h = blockIdx.y, b = blockIdx.z;
    int m0 = qb * 128;
    int tid = threadIdx.x, w = tid >> 5, lane = tid & 31, g = lane >> 2, t = lane & 3;
    unsigned sb = smem_u32(asm_);
    const unsigned Qh = sb, Ql = sb + 10240;
    const float hs = 0.17677669529663687f;

    {
        const __nv_bfloat16* qh = g_qkh + ((size_t)b * NW + m0) * 768 + h * 96;
        const __nv_bfloat16* ql = g_qkl + ((size_t)b * NW + m0) * 768 + h * 96;
#pragma unroll
        for (int it = 0; it < 2; it++) {
            int idx = tid + it * 256;
            int row = idx >> 2, q = idx & 3;
            uint4 vh = *(const uint4*)(qh + (size_t)row * 768 + q * 8);
            uint4 vl = *(const uint4*)(ql + (size_t)row * 768 + q * 8);
            *(uint4*)(asm_ + row * 80 + q * 16) = vh;
            *(uint4*)(asm_ + 10240 + row * 80 + q * 16) = vl;
        }
    }
#pragma unroll
    for (int s = 0; s < 2; s++)
        for (int idx = tid; idx < 544; idx += 256) {
            int row = 32 + idx / 68, wd = idx % 68;
            ((unsigned*)(asm_ + 20480 + s * ATT_STAGE + 20480))[row * 68 + wd] =
                (row == 32 && wd < 64) ? 0x3F803F80u : 0u;
            ((unsigned*)(asm_ + 20480 + s * ATT_STAGE + 31360))[row * 68 + wd] = 0u;
        }
    __syncthreads();
    unsigned ah[2][4], al[2][4];
    {
        unsigned qa = Qh + (unsigned)(w * 16 + g) * 80 + t * 4;
        unsigned qa_l = Ql + (unsigned)(w * 16 + g) * 80 + t * 4;
#pragma unroll
        for (int kt2 = 0; kt2 < 2; kt2++) {
            unsigned o = kt2 * 32;
            ah[kt2][0] = lds32(qa + o);       ah[kt2][1] = lds32(qa + o + 640);
            ah[kt2][2] = lds32(qa + o + 16);  ah[kt2][3] = lds32(qa + o + 656);
            al[kt2][0] = lds32(qa_l + o);      al[kt2][1] = lds32(qa_l + o + 640);
            al[kt2][2] = lds32(qa_l + o + 16); al[kt2][3] = lds32(qa_l + o + 656);
        }
    }

    float O[5][4];
#pragma unroll
    for (int v = 0; v < 5; v++)
#pragma unroll
        for (int j = 0; j < 4; j++) O[v][j] = 0.f;

    int krow = tid >> 2, kq = tid & 3;
    const __nv_bfloat16* khb = g_qkh + (size_t)b * NW * 768 + h * 96 + 32;
    const __nv_bfloat16* klb = g_qkl + (size_t)b * NW * 768 + h * 96 + 32;
    int vd = tid >> 3, vseg = tid & 7;
    const unsigned short* vthb = g_vTh + (((size_t)b * 8 + h) * 32 + vd) * 1024 + vseg * 16;
    const unsigned short* vtlb = g_vTl + (((size_t)b * 8 + h) * 32 + vd) * 1024 + vseg * 16;

#define ATT_ISSUE(kt, s) do {                                                  \
    size_t nn = (size_t)(kt) * 128;                                            \
    unsigned ks_ = sb + 20480 + (s) * ATT_STAGE;                               \
    CPA16(ks_ + krow * 80 + kq * 16,               khb + (nn + krow) * 768 + kq * 8);      \
    CPA16(ks_ + 10240 + krow * 80 + kq * 16,       klb + (nn + krow) * 768 + kq * 8);      \
    CPA16(ks_ + (krow + 64) * 80 + kq * 16,        khb + (nn + krow + 64) * 768 + kq * 8); \
    CPA16(ks_ + 10240 + (krow + 64) * 80 + kq * 16, klb + (nn + krow + 64) * 768 + kq * 8);\
    CPA16(ks_ + 20480 + vd * 272 + vseg * 32,      vthb + nn);                 \
    CPA16(ks_ + 20480 + vd * 272 + vseg * 32 + 16, vthb + nn + 8);             \
    CPA16(ks_ + 31360 + vd * 272 + vseg * 32,      vtlb + nn);                 \
    CPA16(ks_ + 31360 + vd * 272 + vseg * 32 + 16, vtlb + nn + 8);             \
    CPA_COMMIT();                                                              \
} while (0)

    ATT_ISSUE(0, 0);
#pragma unroll 1
    for (int kt = 0; kt < 8; kt++) {
        if (kt < 7) { ATT_ISSUE(kt + 1, (kt + 1) & 1); CPA_WAIT(1); }
        else        { CPA_WAIT(0); }
        __syncthreads();
        unsigned ksb = sb + 20480 + (kt & 1) * ATT_STAGE;
        unsigned KhS = ksb, KlS = ksb + 10240, VhS = ksb + 20480, VlS = ksb + 31360;

        unsigned pa_h[8][4], pa_l[8][4];
#pragma unroll
        for (int j = 0; j < 16; j++) {
            float s[4] = {0.f, 0.f, 0.f, 0.f};
            unsigned kbase = KhS + (unsigned)(j * 8 + g) * 80 + t * 4;
            unsigned kbase_l = KlS + (unsigned)(j * 8 + g) * 80 + t * 4;
#pragma unroll
            for (int kt2 = 0; kt2 < 2; kt2++) {
                unsigned o = kt2 * 32;
                unsigned bh[2] = {lds32(kbase + o), lds32(kbase + o + 16)};
                unsigned bl[2] = {lds32(kbase_l + o), lds32(kbase_l + o + 16)};
                mma16816(s, ah[kt2], bh);
                mma16816(s, ah[kt2], bl);
                mma16816(s, al[kt2], bh);
            }
            float p0 = __expf(s[0] * hs), p1 = __expf(s[1] * hs);
            float p2 = __expf(s[2] * hs), p3 = __expf(s[3] * hs);
            unsigned h01 = pack_bf16x2(p0, p1);
            unsigned h23 = pack_bf16x2(p2, p3);
            unsigned l01 = pack_bf16x2(p0 - __uint_as_float(h01 << 16),
                                       p1 - __uint_as_float(h01 & 0xffff0000u));
            unsigned l23 = pack_bf16x2(p2 - __uint_as_float(h23 << 16),
                                       p3 - __uint_as_float(h23 & 0xffff0000u));
            int kk = j >> 1, hf = (j & 1) * 2;
            pa_h[kk][hf] = h01; pa_h[kk][hf + 1] = h23;
            pa_l[kk][hf] = l01; pa_l[kk][hf + 1] = l23;
        }
#pragma unroll
        for (int v = 0; v < 5; v++) {
            unsigned vb = VhS + (unsigned)(v * 8 + g) * 272 + t * 4;
            unsigned vb_l = VlS + (unsigned)(v * 8 + g) * 272 + t * 4;
#pragma unroll
            for (int kk = 0; kk < 8; kk++) {
                unsigned o = kk * 32;
                unsigned bh[2] = {lds32(vb + o), lds32(vb + o + 16)};
                unsigned bl[2] = {lds32(vb_l + o), lds32(vb_l + o + 16)};
                mma16816(O[v], pa_h[kk], bh);
                mma16816(O[v], pa_h[kk], bl);
                mma16816(O[v], pa_l[kk], bh);
            }
        }
        __syncthreads();
    }
#undef ATT_ISSUE
    float lg = __shfl_sync(0xffffffffu, O[4][0], lane & 28);
    float lg8 = __shfl_sync(0xffffffffu, O[4][2], lane & 28);
    float inv = 1.f / lg, inv8 = 1.f / lg8;
    size_t ob = ((size_t)b * NW + m0 + w * 16 + g) * 256 + h * 32;
    size_t ob8 = ob + (size_t)8 * 256;
#pragma unroll
    for (int v = 0; v < 4; v++) {
        int d = v * 8 + t * 2;
        float x0 = O[v][0] * inv, x1 = O[v][1] * inv;
        float x2 = O[v][2] * inv8, x3 = O[v][3] * inv8;
        unsigned hp0 = pack_bf16x2(x0, x1);
        unsigned lp0 = pack_bf16x2(x0 - __uint_as_float(hp0 << 16),
                                   x1 - __uint_as_float(hp0 & 0xffff0000u));
        unsigned hp1 = pack_bf16x2(x2, x3);
        unsigned lp1 = pack_bf16x2(x2 - __uint_as_float(hp1 << 16),
                                   x3 - __uint_as_float(hp1 & 0xffff0000u));
        *(unsigned*)&g_aoh[ob + d] = hp0;
        *(unsigned*)&g_aol[ob + d] = lp0;
        *(unsigned*)&g_aoh[ob8 + d] = hp1;
        *(unsigned*)&g_aol[ob8 + d] = lp1;
    }
}

// ---------------- kernel 7: scatter, hoisted r-loads ------------------------
__global__ void scatter_kernel(float* __restrict__ out) {
    __shared__ float aff_s[32 * 144];
    __shared__ float r_s[3 * 34 * 33];
    int Y = blockIdx.x, b = blockIdx.y;
    int tid = threadIdx.x;
    int X = tid >> 2, px = tid & 3;
    const float* ab = g_aff + ((size_t)b * NW + Y * 32) * 144;
    for (int idx = tid; idx < 4608; idx += 128) aff_s[idx] = ab[idx];
    for (int idx = tid; idx < 3 * 34 * 33; idx += 128) r_s[idx] = 0.f;
    __syncthreads();
    float a[4][9];
#pragma unroll
    for (int py = 0; py < 4; py++)
#pragma unroll
        for (int i = 0; i < 9; i++)
            a[py][i] = aff_s[X * 144 + (py * 4 + px) * 9 + i];

    for (int c0 = 0; c0 < 256; c0 += 32) {
        __syncthreads();
        for (int idx = tid; idx < 3 * 32 * 32; idx += 128) {
            int dy = idx >> 10;
            int rem = idx & 1023;
            int Xl = rem >> 5, cc = rem & 31;
            int ny = Y + dy - 1;
            if ((unsigned)ny < 32u)
                r_s[((dy * 34) + Xl + 1) * 33 + cc] =
                    g_proj[((size_t)b * NW + ny * 32 + Xl) * Cv + c0 + cc];
        }
        __syncthreads();
#pragma unroll 4
        for (int c = 0; c < 32; c++) {
            float r[9];
#pragma unroll
            for (int i = 0; i < 9; i++) {
                int dy = i / 3, dx = i % 3;
                r[i] = r_s[((dy * 34) + X + dx) * 33 + c];
            }
            size_t obase = ((size_t)b * 256 + c0 + c) * 16384 +
                           (size_t)(Y * 4) * 128 + tid;
#pragma unroll
            for (int py = 0; py < 4; py++) {
                float v = 0.f;
#pragma unroll
                for (int i = 0; i < 9; i++) v = fmaf(r[i], a[py][i], v);
                out[obase + (size_t)py * 128] = v;
            }
        }
    }
}

// ---------------- launch ----------------
extern "C" void kernel_launch(void* const* d_in, const int* in_sizes, int n_in,
                              void* d_out, int out_size) {
    const float* x = nullptr; const float* qkv_w = nullptr;
    const float* proj_w = nullptr; const float* proj_b = nullptr;
    for (int i = 0; i < n_in; i++) {
        int s = in_sizes[i];
        if (s == 8 * 16384 * 256) x = (const float*)d_in[i];
        else if (s == 768 * 256)  qkv_w = (const float*)d_in[i];
        else if (s == 256 * 256)  proj_w = (const float*)d_in[i];
        else if (s == 256)        proj_b = (const float*)d_in[i];
    }
    float* out = (float*)d_out;

    const int DSMEM = 2 * STG_STRIDE;
    cudaFuncSetAttribute(gemm_mma, cudaFuncAttributeMaxDynamicSharedMemorySize, DSMEM);
    cudaFuncSetAttribute(attn_mma, cudaFuncAttributeMaxDynamicSharedMemorySize, ATT_SMEM);

    pool_kernel<<<dim3(256, 8), 256>>>(x);
    conv_w<<<768, 256>>>(qkv_w, proj_w);
    aff_kernel<<<dim3(1024, 8), 256>>>(x);
    fold_kernel<<<dim3(256, 8), 256>>>();
    gemm_mma<<<dim3(8, 6, 8), 256, DSMEM>>>(0, nullptr, 768);
    attn_mma<<<dim3(8, 8, 8), 256, ATT_SMEM>>>();
    gemm_mma<<<dim3(8, 2, 8), 256, DSMEM>>>(1, proj_b, 256);
    scatter_kernel<<<dim3(32, 8), 128>>>(out);
}

// round 15
// speedup vs baseline: 1.0464x; 1.0464x over previous
#include <cuda_runtime.h>
#include <cuda_bf16.h>
#include <math.h>
#include <stdint.h>

#define Bv 8
#define Cv 256
#define NW 1024      // 32*32 super tokens
#define NHEADS 8
#define HD 32

// ---------------- scratch (static device memory; no allocs) ----------------
__device__ float g_wf[Bv * NW * Cv];                 // (b, t, c)
__device__ float g_aff[Bv * NW * 16 * 9];            // (b, t, p, i)
__device__ float g_wf2raw[(size_t)Bv * NW * 9 * Cv]; // (b, t, i, c)
__device__ float g_affsumraw[Bv * NW * 9];           // (b, t, i)
__device__ __nv_bfloat16 g_wf2h[Bv * NW * Cv];       // tokens hi (b, t, c)
__device__ __nv_bfloat16 g_wf2l[Bv * NW * Cv];       // tokens lo
__device__ __nv_bfloat16 g_qkvwh[768 * 256];         // qkv weight hi (o,k)
__device__ __nv_bfloat16 g_qkvwl[768 * 256];
__device__ __nv_bfloat16 g_pwh[256 * 256];           // proj weight hi (o,k)
__device__ __nv_bfloat16 g_pwl[256 * 256];
__device__ __nv_bfloat16 g_qkh[(size_t)Bv * NW * 768];  // qkv out hi (b, n, o)
__device__ __nv_bfloat16 g_qkl[(size_t)Bv * NW * 768];  // qkv out lo
__device__ unsigned short g_vTh[(size_t)Bv * 8 * 32 * 1024]; // V^T hi (b,h,d,n)
__device__ unsigned short g_vTl[(size_t)Bv * 8 * 32 * 1024]; // V^T lo
__device__ __nv_bfloat16 g_aoh[Bv * NW * Cv];        // attn out hi (b, n, c)
__device__ __nv_bfloat16 g_aol[Bv * NW * Cv];        // attn out lo
__device__ float g_proj[(size_t)Bv * NW * Cv];       // (b, n, o)

// ---------------- f32x2 packed-math helpers (sm_103a) ----------------
typedef unsigned long long u64;
__device__ __forceinline__ u64 f2_dup(float a) {
    u64 d; asm("mov.b64 %0, {%1, %1};" : "=l"(d) : "f"(a)); return d;
}
__device__ __forceinline__ void f2_unpack(float& a, float& b, u64 d) {
    asm("mov.b64 {%0, %1}, %2;" : "=f"(a), "=f"(b) : "l"(d));
}
__device__ __forceinline__ void fma2(u64& c, u64 a, u64 b) {
    asm("fma.rn.f32x2 %0, %1, %2, %0;" : "+l"(c) : "l"(a), "l"(b));
}
__device__ __forceinline__ u64 lds64(unsigned saddr) {
    u64 v;
    asm volatile("ld.shared.b64 %0, [%1];" : "=l"(v) : "r"(saddr));
    return v;
}
__device__ __forceinline__ unsigned lds32(unsigned saddr) {
    unsigned v;
    asm volatile("ld.shared.b32 %0, [%1];" : "=r"(v) : "r"(saddr));
    return v;
}
__device__ __forceinline__ unsigned smem_u32(const void* p) {
    unsigned a;
    asm("{ .reg .u64 t; cvta.to.shared.u64 t, %1; cvt.u32.u64 %0, t; }" : "=r"(a) : "l"(p));
    return a;
}
// pack: low half = lo, high half = hi (PTX: first src -> upper)
__device__ __forceinline__ unsigned pack_bf16x2(float lo, float hi) {
    unsigned d;
    asm("cvt.rn.bf16x2.f32 %0, %1, %2;" : "=r"(d) : "f"(hi), "f"(lo));
    return d;
}

// ---------------- mma.sync + cp.async helpers (portable sm_80+) -------------
__device__ __forceinline__ void mma16816(float* c, const unsigned* a, const unsigned* b) {
    asm volatile(
        "mma.sync.aligned.m16n8k16.row.col.f32.bf16.bf16.f32 "
        "{%0,%1,%2,%3}, {%4,%5,%6,%7}, {%8,%9}, {%0,%1,%2,%3};"
        : "+f"(c[0]), "+f"(c[1]), "+f"(c[2]), "+f"(c[3])
        : "r"(a[0]), "r"(a[1]), "r"(a[2]), "r"(a[3]), "r"(b[0]), "r"(b[1]));
}
#define CPA16(dst, src) \
    asm volatile("cp.async.ca.shared.global [%0], [%1], 16;" :: "r"(dst), "l"(src))
#define CPA_COMMIT() asm volatile("cp.async.commit_group;" ::: "memory")
#define CPA_WAIT(n)  asm volatile("cp.async.wait_group %0;" :: "n"(n) : "memory")

// ---------------- kernel 1: 4x4 average pool -> wf (float4) ----------------
__global__ void pool_kernel(const float* __restrict__ x) {
    int b = blockIdx.y;
    int t = blockIdx.x * 4 + (threadIdx.x >> 6);
    int c4 = (threadIdx.x & 63) * 4;
    int Y = t >> 5, X = t & 31;
    const float* xb = x + (size_t)b * 16384 * 256;
    float4 s = make_float4(0.f, 0.f, 0.f, 0.f);
#pragma unroll
    for (int py = 0; py < 4; py++)
#pragma unroll
        for (int px = 0; px < 4; px++) {
            int n = (Y * 4 + py) * 128 + X * 4 + px;
            float4 v = *(const float4*)&xb[(size_t)n * 256 + c4];
            s.x += v.x; s.y += v.y; s.z += v.z; s.w += v.w;
        }
    s.x *= (1.f / 16.f); s.y *= (1.f / 16.f); s.z *= (1.f / 16.f); s.w *= (1.f / 16.f);
    *(float4*)&g_wf[((size_t)b * NW + t) * Cv + c4] = s;
}

// ---------------- weight conversion: fp32 -> bf16 hi/lo (both weights) ------
__global__ void conv_w(const float* __restrict__ qw, const float* __restrict__ pw) {
    int i = blockIdx.x * 256 + threadIdx.x;
    if (i < 768 * 256) {
        float x = qw[i];
        __nv_bfloat16 h = __float2bfloat16(x);
        g_qkvwh[i] = h;
        g_qkvwl[i] = __float2bfloat16(x - __bfloat162float(h));
    }
    if (i < 256 * 256) {
        float x = pw[i];
        __nv_bfloat16 h = __float2bfloat16(x);
        g_pwh[i] = h;
        g_pwl[i] = __float2bfloat16(x - __bfloat162float(h));
    }
}

// ---------------- kernel 2: affinity softmax + wf2 window partials ----------
// Dot phase: warp owns 2 p-rows; pix register-cached; paired-half reduction.
__global__ void aff_kernel(const float* __restrict__ x) {
    __shared__ float pix[16][256];
    __shared__ float wfu[9][256];
    __shared__ float lg[16][9];
    __shared__ float affs[16][9];
    int b = blockIdx.y, t = blockIdx.x, tid = threadIdx.x;
    int Y = t >> 5, X = t & 31;
    const float* xb = x + (size_t)b * 16384 * 256;
    {
        int c4 = (tid & 63) * 4;
#pragma unroll
        for (int pp = 0; pp < 4; pp++) {
            int p = pp * 4 + (tid >> 6);
            int n = (Y * 4 + (p >> 2)) * 128 + X * 4 + (p & 3);
            *(float4*)&pix[p][c4] = *(const float4*)&xb[(size_t)n * 256 + c4];
        }
#pragma unroll
        for (int ii = 0; ii < 3; ii++) {
            int i = ii * 4 + (tid >> 6);
            if (i < 9) {
                int ny = Y + (i / 3) - 1, nx = X + (i % 3) - 1;
                float4 v = make_float4(0.f, 0.f, 0.f, 0.f);
                if ((unsigned)ny < 32u && (unsigned)nx < 32u)
                    v = *(const float4*)&g_wf[((size_t)b * NW + ny * 32 + nx) * Cv + c4];
                *(float4*)&wfu[i][c4] = v;
            }
        }
    }
    __syncthreads();
    int warp = tid >> 5, lane = tid & 31;
    {
        int p0 = warp * 2, p1 = p0 + 1;
        unsigned pixb = smem_u32(&pix[0][0]) + (unsigned)lane * 8 + (unsigned)p0 * 1024;
        unsigned wfub = smem_u32(&wfu[0][0]) + (unsigned)lane * 8;
        u64 pr0[4], pr1[4];
#pragma unroll
        for (int k = 0; k < 4; k++) {
            pr0[k] = lds64(pixb + k * 256);
            pr1[k] = lds64(pixb + 1024 + k * 256);
        }
#pragma unroll
        for (int i = 0; i < 9; i++) {
            u64 s0 = 0ull, s1 = 0ull;
#pragma unroll
            for (int k = 0; k < 4; k++) {
                u64 wf = lds64(wfub + i * 1024 + k * 256);
                fma2(s0, pr0[k], wf);
                fma2(s1, pr1[k], wf);
            }
            float a0, c0, a1, c1;
            f2_unpack(a0, c0, s0);
            f2_unpack(a1, c1, s1);
            float v0 = a0 + c0, v1 = a1 + c1;
            float td = __shfl_down_sync(0xffffffffu, v0, 16);
            float tu = __shfl_up_sync(0xffffffffu, v1, 16);
            float wv = (lane < 16) ? (v0 + td) : (v1 + tu);
#pragma unroll
            for (int off = 8; off; off >>= 1)
                wv += __shfl_down_sync(0xffffffffu, wv, off);
            if (lane == 0)  lg[p0][i] = wv * 0.0625f;
            if (lane == 16) lg[p1][i] = wv * 0.0625f;
        }
    }
    __syncthreads();
    if (tid < 16) {
        float m = -1e30f;
#pragma unroll
        for (int i = 0; i < 9; i++) m = fmaxf(m, lg[tid][i]);
        float e[9], sum = 0.f;
#pragma unroll
        for (int i = 0; i < 9; i++) { e[i] = __expf(lg[tid][i] - m); sum += e[i]; }
        float inv = 1.f / sum;
#pragma unroll
        for (int i = 0; i < 9; i++) affs[tid][i] = e[i] * inv;
    }
    __syncthreads();
    if (tid < 144)
        g_aff[((size_t)b * NW + t) * 144 + tid] = affs[tid / 9][tid % 9];
    if (tid >= 160 && tid < 169) {
        int i = tid - 160;
        float s = 0.f;
#pragma unroll
        for (int p = 0; p < 16; p++) s += affs[p][i];
        g_affsumraw[((size_t)b * NW + t) * 9 + i] = s;
    }
    float acc[9];
#pragma unroll
    for (int i = 0; i < 9; i++) acc[i] = 0.f;
#pragma unroll
    for (int p = 0; p < 16; p++) {
        float v = pix[p][tid];
#pragma unroll
        for (int i = 0; i < 9; i++) acc[i] = fmaf(v, affs[p][i], acc[i]);
    }
    size_t base = ((size_t)b * NW + t) * 9 * Cv;
#pragma unroll
    for (int i = 0; i < 9; i++) g_wf2raw[base + (size_t)i * Cv + tid] = acc[i];
}

// ---------------- kernel 3: fold-gather + normalize -> bf16 hi/lo -----------
__global__ void fold_kernel() {
    int b = blockIdx.y;
    int t = blockIdx.x * 4 + (threadIdx.x >> 6);
    int c = (threadIdx.x & 63) * 4;
    int Y = t >> 5, X = t & 31;
    float4 acc = make_float4(0.f, 0.f, 0.f, 0.f);
    float asum = 0.f;
#pragma unroll
    for (int i = 0; i < 9; i++) {
        int ny = Y - ((i / 3) - 1), nx = X - ((i % 3) - 1);
        if ((unsigned)ny < 32u && (unsigned)nx < 32u) {
            size_t nb = (size_t)b * NW + ny * 32 + nx;
            float4 v = *(const float4*)&g_wf2raw[(nb * 9 + i) * Cv + c];
            acc.x += v.x; acc.y += v.y; acc.z += v.z; acc.w += v.w;
            asum += g_affsumraw[nb * 9 + i];
        }
    }
    float inv = 1.f / (asum + 1e-12f);
    float f[4] = {acc.x * inv, acc.y * inv, acc.z * inv, acc.w * inv};
    size_t off = ((size_t)b * NW + t) * Cv + c;
    __nv_bfloat162 h01, h23, l01, l23;
    h01.x = __float2bfloat16(f[0]); h01.y = __float2bfloat16(f[1]);
    h23.x = __float2bfloat16(f[2]); h23.y = __float2bfloat16(f[3]);
    l01.x = __float2bfloat16(f[0] - __bfloat162float(h01.x));
    l01.y = __float2bfloat16(f[1] - __bfloat162float(h01.y));
    l23.x = __float2bfloat16(f[2] - __bfloat162float(h23.x));
    l23.y = __float2bfloat16(f[3] - __bfloat162float(h23.y));
    *(__nv_bfloat162*)&g_wf2h[off] = h01;
    *(__nv_bfloat162*)&g_wf2h[off + 2] = h23;
    *(__nv_bfloat162*)&g_wf2l[off] = l01;
    *(__nv_bfloat162*)&g_wf2l[off + 2] = l23;
}

// ---------------- GEMM via mma.sync bf16 (3-term hi/lo split) ---------------
// which==0 (qkv): out bf16 hi/lo token-major + smem-transposed coalesced V^T.
// which==1 (proj): f32+bias.
#define STG_STRIDE 40960
__global__ void __launch_bounds__(256) gemm_mma(int which,
                                                const float* __restrict__ bias,
                                                int outStride) {
    extern __shared__ __align__(16) char sm[];
    int b = blockIdx.z;
    int n0 = blockIdx.x * 128, o0 = blockIdx.y * 128;
    int tid = threadIdx.x;
    int w = tid >> 5, lane = tid & 31, g = lane >> 2, t = lane & 3;
    int wm = (w >> 2) * 64, wn = (w & 3) * 32;

    const __nv_bfloat16* Ah = (which == 0 ? g_wf2h : g_aoh) + (size_t)b * NW * Cv;
    const __nv_bfloat16* Al = (which == 0 ? g_wf2l : g_aol) + (size_t)b * NW * Cv;
    const __nv_bfloat16* Bh = (which == 0 ? g_qkvwh : g_pwh);
    const __nv_bfloat16* Bl = (which == 0 ? g_qkvwl : g_pwl);

    unsigned smb = smem_u32(sm);
    int lr0 = tid >> 2, lq = tid & 3;
    int lr1 = lr0 + 64;
    unsigned sd0 = lr0 * 80 + lq * 16;
    unsigned sd1 = lr1 * 80 + lq * 16;

    float acc[4][4][4];
#pragma unroll
    for (int mt = 0; mt < 4; mt++)
#pragma unroll
        for (int nt = 0; nt < 4; nt++)
#pragma unroll
            for (int j = 0; j < 4; j++) acc[mt][nt][j] = 0.f;

#define ISSUE_CHUNK(kc, s) do {                                                \
    unsigned sb = smb + (s) * STG_STRIDE;                                      \
    size_t ga0 = (size_t)(n0 + lr0) * 256 + (kc) * 32 + lq * 8;                \
    size_t ga1 = (size_t)(n0 + lr1) * 256 + (kc) * 32 + lq * 8;                \
    size_t gb0 = (size_t)(o0 + lr0) * 256 + (kc) * 32 + lq * 8;                \
    size_t gb1 = (size_t)(o0 + lr1) * 256 + (kc) * 32 + lq * 8;                \
    CPA16(sb + sd0,         Ah + ga0);  CPA16(sb + sd1,         Ah + ga1);     \
    CPA16(sb + 10240 + sd0, Al + ga0);  CPA16(sb + 10240 + sd1, Al + ga1);     \
    CPA16(sb + 20480 + sd0, Bh + gb0);  CPA16(sb + 20480 + sd1, Bh + gb1);     \
    CPA16(sb + 30720 + sd0, Bl + gb0);  CPA16(sb + 30720 + sd1, Bl + gb1);     \
    CPA_COMMIT();                                                              \
} while (0)

    ISSUE_CHUNK(0, 0);
    ISSUE_CHUNK(1, 1);
#pragma unroll 1
    for (int c = 0; c < 8; c++) {
        if (c < 7) { CPA_WAIT(1); } else { CPA_WAIT(0); }
        __syncthreads();
        unsigned stage = smb + (c & 1) * STG_STRIDE;
#pragma unroll
        for (int ks = 0; ks < 2; ks++) {
            unsigned kb = ks * 32;
            unsigned bhf[4][2], blf[4][2];
#pragma unroll
            for (int nt = 0; nt < 4; nt++) {
                unsigned ba = stage + 20480 + (unsigned)(wn + nt * 8 + g) * 80 + t * 4 + kb;
                bhf[nt][0] = lds32(ba);          bhf[nt][1] = lds32(ba + 16);
                blf[nt][0] = lds32(ba + 10240);  blf[nt][1] = lds32(ba + 10256);
            }
#pragma unroll
            for (int mt = 0; mt < 4; mt++) {
                unsigned aa = stage + (unsigned)(wm + mt * 16 + g) * 80 + t * 4 + kb;
                unsigned ahf[4], alf[4];
                ahf[0] = lds32(aa);        ahf[1] = lds32(aa + 640);
                ahf[2] = lds32(aa + 16);   ahf[3] = lds32(aa + 656);
                alf[0] = lds32(aa + 10240);        alf[1] = lds32(aa + 10880);
                alf[2] = lds32(aa + 10256);        alf[3] = lds32(aa + 10896);
#pragma unroll
                for (int nt = 0; nt < 4; nt++) {
                    mma16816(acc[mt][nt], ahf, bhf[nt]);
                    mma16816(acc[mt][nt], ahf, blf[nt]);
                    mma16816(acc[mt][nt], alf, bhf[nt]);
                }
            }
        }
        __syncthreads();
        if (c < 6) ISSUE_CHUNK(c + 2, c & 1);
    }
#undef ISSUE_CHUNK

    if (which == 1) {
#pragma unroll
        for (int nt = 0; nt < 4; nt++) {
            int col = o0 + wn + nt * 8 + t * 2;
            float b0 = __ldg(&bias[col]), b1 = __ldg(&bias[col + 1]);
#pragma unroll
            for (int mt = 0; mt < 4; mt++) {
                int row = n0 + wm + mt * 16 + g;
                float* p = g_proj + ((size_t)b * NW + row) * 256 + col;
                *(float2*)p = make_float2(acc[mt][nt][0] + b0, acc[mt][nt][1] + b1);
                *(float2*)(p + (size_t)8 * 256) =
                    make_float2(acc[mt][nt][2] + b0, acc[mt][nt][3] + b1);
            }
        }
    } else {
        // qk token-major writes + V^T staged via smem (pitch 136 ushort, 16B rows)
        unsigned short* vtb_h = (unsigned short*)sm;            // [128][136]
        unsigned short* vtb_l = (unsigned short*)(sm + 34816);  // [128][136]
#pragma unroll
        for (int nt = 0; nt < 4; nt++) {
            int colL = wn + nt * 8 + t * 2;
            int col = o0 + colL;
#pragma unroll
            for (int mt = 0; mt < 4; mt++) {
#pragma unroll
                for (int rr = 0; rr < 2; rr++) {
                    int rl = wm + mt * 16 + g + rr * 8;
                    float v0 = acc[mt][nt][rr * 2], v1 = acc[mt][nt][rr * 2 + 1];
                    unsigned hpair = pack_bf16x2(v0, v1);
                    float h0f = __uint_as_float(hpair << 16);
                    float h1f = __uint_as_float(hpair & 0xffff0000u);
                    unsigned lpair = pack_bf16x2(v0 - h0f, v1 - h1f);
                    size_t oo = ((size_t)b * NW + n0 + rl) * 768 + col;
                    *(unsigned*)&g_qkh[oo] = hpair;
                    *(unsigned*)&g_qkl[oo] = lpair;
                    vtb_h[colL * 136 + rl] = (unsigned short)(hpair & 0xffffu);
                    vtb_h[(colL + 1) * 136 + rl] = (unsigned short)(hpair >> 16);
                    vtb_l[colL * 136 + rl] = (unsigned short)(lpair & 0xffffu);
                    vtb_l[(colL + 1) * 136 + rl] = (unsigned short)(lpair >> 16);
                }
            }
        }
        __syncthreads();
        // coalesced V^T writes: rows that are V columns (col%96 >= 64)
#pragma unroll
        for (int it = 0; it < 8; it++) {
            int idx = tid + it * 256;
            int row = idx >> 4, seg = idx & 15;
            int col = o0 + row;
            int cm = col % 96, hh = col / 96;
            if (cm >= 64) {
                size_t vb = (((size_t)b * 8 + hh) * 32 + (cm - 64)) * 1024 + n0 + seg * 8;
                *(uint4*)&g_vTh[vb] = *(uint4*)&vtb_h[row * 136 + seg * 8];
                *(uint4*)&g_vTl[vb] = *(uint4*)&vtb_l[row * 136 + seg * 8];
            }
        }
    }
}

// ---------------- kernel 5: flash-MMA attention, cp.async double-buffered ---
#define ATT_STAGE 42240
#define ATT_SMEM (20480 + 2 * ATT_STAGE)
__global__ void __launch_bounds__(256) attn_mma() {
    extern __shared__ __align__(16) char asm_[];
    int qb = blockIdx.x, h = blockIdx.y, b = blockIdx.z;
    int m0 = qb * 128;
    int tid = threadIdx.x, w = tid >> 5, lane = tid & 31, g = lane >> 2, t = lane & 3;
    unsigned sb = smem_u32(asm_);
    const unsigned Qh = sb, Ql = sb + 10240;
    const float hs = 0.17677669529663687f;

    {
        const __nv_bfloat16* qh = g_qkh + ((size_t)b * NW + m0) * 768 + h * 96;
        const __nv_bfloat16* ql = g_qkl + ((size_t)b * NW + m0) * 768 + h * 96;
#pragma unroll
        for (int it = 0; it < 2; it++) {
            int idx = tid + it * 256;
            int row = idx >> 2, q = idx & 3;
            uint4 vh = *(const uint4*)(qh + (size_t)row * 768 + q * 8);
            uint4 vl = *(const uint4*)(ql + (size_t)row * 768 + q * 8);
            *(uint4*)(asm_ + row * 80 + q * 16) = vh;
            *(uint4*)(asm_ + 10240 + row * 80 + q * 16) = vl;
        }
    }
#pragma unroll
    for (int s = 0; s < 2; s++)
        for (int idx = tid; idx < 544; idx += 256) {
            int row = 32 + idx / 68, wd = idx % 68;
            ((unsigned*)(asm_ + 20480 + s * ATT_STAGE + 20480))[row * 68 + wd] =
                (row == 32 && wd < 64) ? 0x3F803F80u : 0u;
            ((unsigned*)(asm_ + 20480 + s * ATT_STAGE + 31360))[row * 68 + wd] = 0u;
        }
    __syncthreads();
    unsigned ah[2][4], al[2][4];
    {
        unsigned qa = Qh + (unsigned)(w * 16 + g) * 80 + t * 4;
        unsigned qa_l = Ql + (unsigned)(w * 16 + g) * 80 + t * 4;
#pragma unroll
        for (int kt2 = 0; kt2 < 2; kt2++) {
            unsigned o = kt2 * 32;
            ah[kt2][0] = lds32(qa + o);       ah[kt2][1] = lds32(qa + o + 640);
            ah[kt2][2] = lds32(qa + o + 16);  ah[kt2][3] = lds32(qa + o + 656);
            al[kt2][0] = lds32(qa_l + o);      al[kt2][1] = lds32(qa_l + o + 640);
            al[kt2][2] = lds32(qa_l + o + 16); al[kt2][3] = lds32(qa_l + o + 656);
        }
    }

    float O[5][4];
#pragma unroll
    for (int v = 0; v < 5; v++)
#pragma unroll
        for (int j = 0; j < 4; j++) O[v][j] = 0.f;

    int krow = tid >> 2, kq = tid & 3;
    const __nv_bfloat16* khb = g_qkh + (size_t)b * NW * 768 + h * 96 + 32;
    const __nv_bfloat16* klb = g_qkl + (size_t)b * NW * 768 + h * 96 + 32;
    int vd = tid >> 3, vseg = tid & 7;
    const unsigned short* vthb = g_vTh + (((size_t)b * 8 + h) * 32 + vd) * 1024 + vseg * 16;
    const unsigned short* vtlb = g_vTl + (((size_t)b * 8 + h) * 32 + vd) * 1024 + vseg * 16;

#define ATT_ISSUE(kt, s) do {                                                  \
    size_t nn = (size_t)(kt) * 128;                                            \
    unsigned ks_ = sb + 20480 + (s) * ATT_STAGE;                               \
    CPA16(ks_ + krow * 80 + kq * 16,               khb + (nn + krow) * 768 + kq * 8);      \
    CPA16(ks_ + 10240 + krow * 80 + kq * 16,       klb + (nn + krow) * 768 + kq * 8);      \
    CPA16(ks_ + (krow + 64) * 80 + kq * 16,        khb + (nn + krow + 64) * 768 + kq * 8); \
    CPA16(ks_ + 10240 + (krow + 64) * 80 + kq * 16, klb + (nn + krow + 64) * 768 + kq * 8);\
    CPA16(ks_ + 20480 + vd * 272 + vseg * 32,      vthb + nn);                 \
    CPA16(ks_ + 20480 + vd * 272 + vseg * 32 + 16, vthb + nn + 8);             \
    CPA16(ks_ + 31360 + vd * 272 + vseg * 32,      vtlb + nn);                 \
    CPA16(ks_ + 31360 + vd * 272 + vseg * 32 + 16, vtlb + nn + 8);             \
    CPA_COMMIT();                                                              \
} while (0)

    ATT_ISSUE(0, 0);
#pragma unroll 1
    for (int kt = 0; kt < 8; kt++) {
        if (kt < 7) { ATT_ISSUE(kt + 1, (kt + 1) & 1); CPA_WAIT(1); }
        else        { CPA_WAIT(0); }
        __syncthreads();
        unsigned ksb = sb + 20480 + (kt & 1) * ATT_STAGE;
        unsigned KhS = ksb, KlS = ksb + 10240, VhS = ksb + 20480, VlS = ksb + 31360;

        unsigned pa_h[8][4], pa_l[8][4];
#pragma unroll
        for (int j = 0; j < 16; j++) {
            float s[4] = {0.f, 0.f, 0.f, 0.f};
            unsigned kbase = KhS + (unsigned)(j * 8 + g) * 80 + t * 4;
            unsigned kbase_l = KlS + (unsigned)(j * 8 + g) * 80 + t * 4;
#pragma unroll
            for (int kt2 = 0; kt2 < 2; kt2++) {
                unsigned o = kt2 * 32;
                unsigned bh[2] = {lds32(kbase + o), lds32(kbase + o + 16)};
                unsigned bl[2] = {lds32(kbase_l + o), lds32(kbase_l + o + 16)};
                mma16816(s, ah[kt2], bh);
                mma16816(s, ah[kt2], bl);
                mma16816(s, al[kt2], bh);
            }
            float p0 = __expf(s[0] * hs), p1 = __expf(s[1] * hs);
            float p2 = __expf(s[2] * hs), p3 = __expf(s[3] * hs);
            unsigned h01 = pack_bf16x2(p0, p1);
            unsigned h23 = pack_bf16x2(p2, p3);
            unsigned l01 = pack_bf16x2(p0 - __uint_as_float(h01 << 16),
                                       p1 - __uint_as_float(h01 & 0xffff0000u));
            unsigned l23 = pack_bf16x2(p2 - __uint_as_float(h23 << 16),
                                       p3 - __uint_as_float(h23 & 0xffff0000u));
            int kk = j >> 1, hf = (j & 1) * 2;
            pa_h[kk][hf] = h01; pa_h[kk][hf + 1] = h23;
            pa_l[kk][hf] = l01; pa_l[kk][hf + 1] = l23;
        }
#pragma unroll
        for (int v = 0; v < 5; v++) {
            unsigned vb = VhS + (unsigned)(v * 8 + g) * 272 + t * 4;
            unsigned vb_l = VlS + (unsigned)(v * 8 + g) * 272 + t * 4;
#pragma unroll
            for (int kk = 0; kk < 8; kk++) {
                unsigned o = kk * 32;
                unsigned bh[2] = {lds32(vb + o), lds32(vb + o + 16)};
                unsigned bl[2] = {lds32(vb_l + o), lds32(vb_l + o + 16)};
                mma16816(O[v], pa_h[kk], bh);
                mma16816(O[v], pa_h[kk], bl);
                mma16816(O[v], pa_l[kk], bh);
            }
        }
        __syncthreads();
    }
#undef ATT_ISSUE
    float lg = __shfl_sync(0xffffffffu, O[4][0], lane & 28);
    float lg8 = __shfl_sync(0xffffffffu, O[4][2], lane & 28);
    float inv = 1.f / lg, inv8 = 1.f / lg8;
    size_t ob = ((size_t)b * NW + m0 + w * 16 + g) * 256 + h * 32;
    size_t ob8 = ob + (size_t)8 * 256;
#pragma unroll
    for (int v = 0; v < 4; v++) {
        int d = v * 8 + t * 2;
        float x0 = O[v][0] * inv, x1 = O[v][1] * inv;
        float x2 = O[v][2] * inv8, x3 = O[v][3] * inv8;
        unsigned hp0 = pack_bf16x2(x0, x1);
        unsigned lp0 = pack_bf16x2(x0 - __uint_as_float(hp0 << 16),
                                   x1 - __uint_as_float(hp0 & 0xffff0000u));
        unsigned hp1 = pack_bf16x2(x2, x3);
        unsigned lp1 = pack_bf16x2(x2 - __uint_as_float(hp1 << 16),
                                   x3 - __uint_as_float(hp1 & 0xffff0000u));
        *(unsigned*)&g_aoh[ob + d] = hp0;
        *(unsigned*)&g_aol[ob + d] = lp0;
        *(unsigned*)&g_aoh[ob8 + d] = hp1;
        *(unsigned*)&g_aol[ob8 + d] = lp1;
    }
}

// ---------------- kernel 7: scatter, hoisted r-loads ------------------------
__global__ void scatter_kernel(float* __restrict__ out) {
    __shared__ float aff_s[32 * 144];
    __shared__ float r_s[3 * 34 * 33];
    int Y = blockIdx.x, b = blockIdx.y;
    int tid = threadIdx.x;
    int X = tid >> 2, px = tid & 3;
    const float* ab = g_aff + ((size_t)b * NW + Y * 32) * 144;
    for (int idx = tid; idx < 4608; idx += 128) aff_s[idx] = ab[idx];
    for (int idx = tid; idx < 3 * 34 * 33; idx += 128) r_s[idx] = 0.f;
    __syncthreads();
    float a[4][9];
#pragma unroll
    for (int py = 0; py < 4; py++)
#pragma unroll
        for (int i = 0; i < 9; i++)
            a[py][i] = aff_s[X * 144 + (py * 4 + px) * 9 + i];

    for (int c0 = 0; c0 < 256; c0 += 32) {
        __syncthreads();
        for (int idx = tid; idx < 3 * 32 * 32; idx += 128) {
            int dy = idx >> 10;
            int rem = idx & 1023;
            int Xl = rem >> 5, cc = rem & 31;
            int ny = Y + dy - 1;
            if ((unsigned)ny < 32u)
                r_s[((dy * 34) + Xl + 1) * 33 + cc] =
                    g_proj[((size_t)b * NW + ny * 32 + Xl) * Cv + c0 + cc];
        }
        __syncthreads();
#pragma unroll 4
        for (int c = 0; c < 32; c++) {
            float r[9];
#pragma unroll
            for (int i = 0; i < 9; i++) {
                int dy = i / 3, dx = i % 3;
                r[i] = r_s[((dy * 34) + X + dx) * 33 + c];
            }
            size_t obase = ((size_t)b * 256 + c0 + c) * 16384 +
                           (size_t)(Y * 4) * 128 + tid;
#pragma unroll
            for (int py = 0; py < 4; py++) {
                float v = 0.f;
#pragma unroll
                for (int i = 0; i < 9; i++) v = fmaf(r[i], a[py][i], v);
                out[obase + (size_t)py * 128] = v;
            }
        }
    }
}

// ---------------- launch ----------------
extern "C" void kernel_launch(void* const* d_in, const int* in_sizes, int n_in,
                              void* d_out, int out_size) {
    const float* x = nullptr; const float* qkv_w = nullptr;
    const float* proj_w = nullptr; const float* proj_b = nullptr;
    for (int i = 0; i < n_in; i++) {
        int s = in_sizes[i];
        if (s == 8 * 16384 * 256) x = (const float*)d_in[i];
        else if (s == 768 * 256)  qkv_w = (const float*)d_in[i];
        else if (s == 256 * 256)  proj_w = (const float*)d_in[i];
        else if (s == 256)        proj_b = (const float*)d_in[i];
    }
    float* out = (float*)d_out;

    const int DSMEM = 2 * STG_STRIDE;
    cudaFuncSetAttribute(gemm_mma, cudaFuncAttributeMaxDynamicSharedMemorySize, DSMEM);
    cudaFuncSetAttribute(attn_mma, cudaFuncAttributeMaxDynamicSharedMemorySize, ATT_SMEM);

    pool_kernel<<<dim3(256, 8), 256>>>(x);
    conv_w<<<768, 256>>>(qkv_w, proj_w);
    aff_kernel<<<dim3(1024, 8), 256>>>(x);
    fold_kernel<<<dim3(256, 8), 256>>>();
    gemm_mma<<<dim3(8, 6, 8), 256, DSMEM>>>(0, nullptr, 768);
    attn_mma<<<dim3(8, 8, 8), 256, ATT_SMEM>>>();
    gemm_mma<<<dim3(8, 2, 8), 256, DSMEM>>>(1, proj_b, 256);
    scatter_kernel<<<dim3(32, 8), 128>>>(out);
}

// round 16
// speedup vs baseline: 1.0753x; 1.0276x over previous
#include <cuda_runtime.h>
#include <cuda_bf16.h>
#include <math.h>
#include <stdint.h>

#define Bv 8
#define Cv 256
#define NW 1024      // 32*32 super tokens
#define NHEADS 8
#define HD 32

// ---------------- scratch (static device memory; no allocs) ----------------
__device__ float g_wf[Bv * NW * Cv];                 // (b, t, c)
__device__ float g_aff[Bv * NW * 16 * 9];            // (b, t, p, i)
__device__ float g_wf2raw[(size_t)Bv * NW * 9 * Cv]; // (b, t, i, c)
__device__ float g_affsumraw[Bv * NW * 9];           // (b, t, i)
__device__ __nv_bfloat16 g_wf2h[Bv * NW * Cv];       // tokens hi (b, t, c)
__device__ __nv_bfloat16 g_wf2l[Bv * NW * Cv];       // tokens lo
__device__ __nv_bfloat16 g_qkvwh[768 * 256];         // qkv weight hi (o,k)
__device__ __nv_bfloat16 g_qkvwl[768 * 256];
__device__ __nv_bfloat16 g_pwh[256 * 256];           // proj weight hi (o,k)
__device__ __nv_bfloat16 g_pwl[256 * 256];
__device__ __nv_bfloat16 g_qkh[(size_t)Bv * NW * 768];  // qkv out hi (b, n, o)
__device__ __nv_bfloat16 g_qkl[(size_t)Bv * NW * 768];  // qkv out lo
__device__ unsigned short g_vTh[(size_t)Bv * 8 * 32 * 1024]; // V^T hi (b,h,d,n)
__device__ unsigned short g_vTl[(size_t)Bv * 8 * 32 * 1024]; // V^T lo
__device__ __nv_bfloat16 g_aoh[Bv * NW * Cv];        // attn out hi (b, n, c)
__device__ __nv_bfloat16 g_aol[Bv * NW * Cv];        // attn out lo
__device__ float g_proj[(size_t)Bv * NW * Cv];       // (b, n, o)

// ---------------- f32x2 packed-math helpers (sm_103a) ----------------
typedef unsigned long long u64;
__device__ __forceinline__ u64 f2_dup(float a) {
    u64 d; asm("mov.b64 %0, {%1, %1};" : "=l"(d) : "f"(a)); return d;
}
__device__ __forceinline__ void f2_unpack(float& a, float& b, u64 d) {
    asm("mov.b64 {%0, %1}, %2;" : "=f"(a), "=f"(b) : "l"(d));
}
__device__ __forceinline__ void fma2(u64& c, u64 a, u64 b) {
    asm("fma.rn.f32x2 %0, %1, %2, %0;" : "+l"(c) : "l"(a), "l"(b));
}
__device__ __forceinline__ u64 lds64(unsigned saddr) {
    u64 v;
    asm volatile("ld.shared.b64 %0, [%1];" : "=l"(v) : "r"(saddr));
    return v;
}
__device__ __forceinline__ unsigned lds32(unsigned saddr) {
    unsigned v;
    asm volatile("ld.shared.b32 %0, [%1];" : "=r"(v) : "r"(saddr));
    return v;
}
__device__ __forceinline__ unsigned smem_u32(const void* p) {
    unsigned a;
    asm("{ .reg .u64 t; cvta.to.shared.u64 t, %1; cvt.u32.u64 %0, t; }" : "=r"(a) : "l"(p));
    return a;
}
// pack: low half = lo, high half = hi (PTX: first src -> upper)
__device__ __forceinline__ unsigned pack_bf16x2(float lo, float hi) {
    unsigned d;
    asm("cvt.rn.bf16x2.f32 %0, %1, %2;" : "=r"(d) : "f"(hi), "f"(lo));
    return d;
}

// ---------------- mma.sync + cp.async helpers (portable sm_80+) -------------
__device__ __forceinline__ void mma16816(float* c, const unsigned* a, const unsigned* b) {
    asm volatile(
        "mma.sync.aligned.m16n8k16.row.col.f32.bf16.bf16.f32 "
        "{%0,%1,%2,%3}, {%4,%5,%6,%7}, {%8,%9}, {%0,%1,%2,%3};"
        : "+f"(c[0]), "+f"(c[1]), "+f"(c[2]), "+f"(c[3])
        : "r"(a[0]), "r"(a[1]), "r"(a[2]), "r"(a[3]), "r"(b[0]), "r"(b[1]));
}
#define CPA16(dst, src) \
    asm volatile("cp.async.ca.shared.global [%0], [%1], 16;" :: "r"(dst), "l"(src))
#define CPA_COMMIT() asm volatile("cp.async.commit_group;" ::: "memory")
#define CPA_WAIT(n)  asm volatile("cp.async.wait_group %0;" :: "n"(n) : "memory")

// ---------------- kernel 1: 4x4 average pool -> wf (float4) ----------------
__global__ void pool_kernel(const float* __restrict__ x) {
    int b = blockIdx.y;
    int t = blockIdx.x * 4 + (threadIdx.x >> 6);
    int c4 = (threadIdx.x & 63) * 4;
    int Y = t >> 5, X = t & 31;
    const float* xb = x + (size_t)b * 16384 * 256;
    float4 s = make_float4(0.f, 0.f, 0.f, 0.f);
#pragma unroll
    for (int py = 0; py < 4; py++)
#pragma unroll
        for (int px = 0; px < 4; px++) {
            int n = (Y * 4 + py) * 128 + X * 4 + px;
            float4 v = *(const float4*)&xb[(size_t)n * 256 + c4];
            s.x += v.x; s.y += v.y; s.z += v.z; s.w += v.w;
        }
    s.x *= (1.f / 16.f); s.y *= (1.f / 16.f); s.z *= (1.f / 16.f); s.w *= (1.f / 16.f);
    *(float4*)&g_wf[((size_t)b * NW + t) * Cv + c4] = s;
}

// ---------------- weight conversion: fp32 -> bf16 hi/lo (both weights) ------
__global__ void conv_w(const float* __restrict__ qw, const float* __restrict__ pw) {
    int i = blockIdx.x * 256 + threadIdx.x;
    if (i < 768 * 256) {
        float x = qw[i];
        __nv_bfloat16 h = __float2bfloat16(x);
        g_qkvwh[i] = h;
        g_qkvwl[i] = __float2bfloat16(x - __bfloat162float(h));
    }
    if (i < 256 * 256) {
        float x = pw[i];
        __nv_bfloat16 h = __float2bfloat16(x);
        g_pwh[i] = h;
        g_pwl[i] = __float2bfloat16(x - __bfloat162float(h));
    }
}

// ---------------- kernel 2: affinity softmax + wf2 window partials ----------
// Dot phase: warp owns 2 p-rows; pix register-cached; paired-half reduction.
__global__ void aff_kernel(const float* __restrict__ x) {
    __shared__ float pix[16][256];
    __shared__ float wfu[9][256];
    __shared__ float lg[16][9];
    __shared__ float affs[16][9];
    int b = blockIdx.y, t = blockIdx.x, tid = threadIdx.x;
    int Y = t >> 5, X = t & 31;
    const float* xb = x + (size_t)b * 16384 * 256;
    {
        int c4 = (tid & 63) * 4;
#pragma unroll
        for (int pp = 0; pp < 4; pp++) {
            int p = pp * 4 + (tid >> 6);
            int n = (Y * 4 + (p >> 2)) * 128 + X * 4 + (p & 3);
            *(float4*)&pix[p][c4] = *(const float4*)&xb[(size_t)n * 256 + c4];
        }
#pragma unroll
        for (int ii = 0; ii < 3; ii++) {
            int i = ii * 4 + (tid >> 6);
            if (i < 9) {
                int ny = Y + (i / 3) - 1, nx = X + (i % 3) - 1;
                float4 v = make_float4(0.f, 0.f, 0.f, 0.f);
                if ((unsigned)ny < 32u && (unsigned)nx < 32u)
                    v = *(const float4*)&g_wf[((size_t)b * NW + ny * 32 + nx) * Cv + c4];
                *(float4*)&wfu[i][c4] = v;
            }
        }
    }
    __syncthreads();
    int warp = tid >> 5, lane = tid & 31;
    {
        int p0 = warp * 2, p1 = p0 + 1;
        unsigned pixb = smem_u32(&pix[0][0]) + (unsigned)lane * 8 + (unsigned)p0 * 1024;
        unsigned wfub = smem_u32(&wfu[0][0]) + (unsigned)lane * 8;
        u64 pr0[4], pr1[4];
#pragma unroll
        for (int k = 0; k < 4; k++) {
            pr0[k] = lds64(pixb + k * 256);
            pr1[k] = lds64(pixb + 1024 + k * 256);
        }
#pragma unroll
        for (int i = 0; i < 9; i++) {
            u64 s0 = 0ull, s1 = 0ull;
#pragma unroll
            for (int k = 0; k < 4; k++) {
                u64 wf = lds64(wfub + i * 1024 + k * 256);
                fma2(s0, pr0[k], wf);
                fma2(s1, pr1[k], wf);
            }
            float a0, c0, a1, c1;
            f2_unpack(a0, c0, s0);
            f2_unpack(a1, c1, s1);
            float v0 = a0 + c0, v1 = a1 + c1;
            float td = __shfl_down_sync(0xffffffffu, v0, 16);
            float tu = __shfl_up_sync(0xffffffffu, v1, 16);
            float wv = (lane < 16) ? (v0 + td) : (v1 + tu);
#pragma unroll
            for (int off = 8; off; off >>= 1)
                wv += __shfl_down_sync(0xffffffffu, wv, off);
            if (lane == 0)  lg[p0][i] = wv * 0.0625f;
            if (lane == 16) lg[p1][i] = wv * 0.0625f;
        }
    }
    __syncthreads();
    if (tid < 16) {
        float m = -1e30f;
#pragma unroll
        for (int i = 0; i < 9; i++) m = fmaxf(m, lg[tid][i]);
        float e[9], sum = 0.f;
#pragma unroll
        for (int i = 0; i < 9; i++) { e[i] = __expf(lg[tid][i] - m); sum += e[i]; }
        float inv = 1.f / sum;
#pragma unroll
        for (int i = 0; i < 9; i++) affs[tid][i] = e[i] * inv;
    }
    __syncthreads();
    if (tid < 144)
        g_aff[((size_t)b * NW + t) * 144 + tid] = affs[tid / 9][tid % 9];
    if (tid >= 160 && tid < 169) {
        int i = tid - 160;
        float s = 0.f;
#pragma unroll
        for (int p = 0; p < 16; p++) s += affs[p][i];
        g_affsumraw[((size_t)b * NW + t) * 9 + i] = s;
    }
    float acc[9];
#pragma unroll
    for (int i = 0; i < 9; i++) acc[i] = 0.f;
#pragma unroll
    for (int p = 0; p < 16; p++) {
        float v = pix[p][tid];
#pragma unroll
        for (int i = 0; i < 9; i++) acc[i] = fmaf(v, affs[p][i], acc[i]);
    }
    size_t base = ((size_t)b * NW + t) * 9 * Cv;
#pragma unroll
    for (int i = 0; i < 9; i++) g_wf2raw[base + (size_t)i * Cv + tid] = acc[i];
}

// ---------------- kernel 3: fold-gather + normalize -> bf16 hi/lo -----------
__global__ void fold_kernel() {
    int b = blockIdx.y;
    int t = blockIdx.x * 4 + (threadIdx.x >> 6);
    int c = (threadIdx.x & 63) * 4;
    int Y = t >> 5, X = t & 31;
    float4 acc = make_float4(0.f, 0.f, 0.f, 0.f);
    float asum = 0.f;
#pragma unroll
    for (int i = 0; i < 9; i++) {
        int ny = Y - ((i / 3) - 1), nx = X - ((i % 3) - 1);
        if ((unsigned)ny < 32u && (unsigned)nx < 32u) {
            size_t nb = (size_t)b * NW + ny * 32 + nx;
            float4 v = *(const float4*)&g_wf2raw[(nb * 9 + i) * Cv + c];
            acc.x += v.x; acc.y += v.y; acc.z += v.z; acc.w += v.w;
            asum += g_affsumraw[nb * 9 + i];
        }
    }
    float inv = 1.f / (asum + 1e-12f);
    float f[4] = {acc.x * inv, acc.y * inv, acc.z * inv, acc.w * inv};
    size_t off = ((size_t)b * NW + t) * Cv + c;
    __nv_bfloat162 h01, h23, l01, l23;
    h01.x = __float2bfloat16(f[0]); h01.y = __float2bfloat16(f[1]);
    h23.x = __float2bfloat16(f[2]); h23.y = __float2bfloat16(f[3]);
    l01.x = __float2bfloat16(f[0] - __bfloat162float(h01.x));
    l01.y = __float2bfloat16(f[1] - __bfloat162float(h01.y));
    l23.x = __float2bfloat16(f[2] - __bfloat162float(h23.x));
    l23.y = __float2bfloat16(f[3] - __bfloat162float(h23.y));
    *(__nv_bfloat162*)&g_wf2h[off] = h01;
    *(__nv_bfloat162*)&g_wf2h[off + 2] = h23;
    *(__nv_bfloat162*)&g_wf2l[off] = l01;
    *(__nv_bfloat162*)&g_wf2l[off + 2] = l23;
}

// ---------------- GEMM via mma.sync bf16 (3-term hi/lo split) ---------------
// which==0 (qkv): out bf16 hi/lo token-major + smem-transposed coalesced V^T.
// which==1 (proj): f32+bias.
#define STG_STRIDE 40960
__global__ void __launch_bounds__(256) gemm_mma(int which,
                                                const float* __restrict__ bias,
                                                int outStride) {
    extern __shared__ __align__(16) char sm[];
    int b = blockIdx.z;
    int n0 = blockIdx.x * 128, o0 = blockIdx.y * 128;
    int tid = threadIdx.x;
    int w = tid >> 5, lane = tid & 31, g = lane >> 2, t = lane & 3;
    int wm = (w >> 2) * 64, wn = (w & 3) * 32;

    const __nv_bfloat16* Ah = (which == 0 ? g_wf2h : g_aoh) + (size_t)b * NW * Cv;
    const __nv_bfloat16* Al = (which == 0 ? g_wf2l : g_aol) + (size_t)b * NW * Cv;
    const __nv_bfloat16* Bh = (which == 0 ? g_qkvwh : g_pwh);
    const __nv_bfloat16* Bl = (which == 0 ? g_qkvwl : g_pwl);

    unsigned smb = smem_u32(sm);
    int lr0 = tid >> 2, lq = tid & 3;
    int lr1 = lr0 + 64;
    unsigned sd0 = lr0 * 80 + lq * 16;
    unsigned sd1 = lr1 * 80 + lq * 16;

    float acc[4][4][4];
#pragma unroll
    for (int mt = 0; mt < 4; mt++)
#pragma unroll
        for (int nt = 0; nt < 4; nt++)
#pragma unroll
            for (int j = 0; j < 4; j++) acc[mt][nt][j] = 0.f;

#define ISSUE_CHUNK(kc, s) do {                                                \
    unsigned sb = smb + (s) * STG_STRIDE;                                      \
    size_t ga0 = (size_t)(n0 + lr0) * 256 + (kc) * 32 + lq * 8;                \
    size_t ga1 = (size_t)(n0 + lr1) * 256 + (kc) * 32 + lq * 8;                \
    size_t gb0 = (size_t)(o0 + lr0) * 256 + (kc) * 32 + lq * 8;                \
    size_t gb1 = (size_t)(o0 + lr1) * 256 + (kc) * 32 + lq * 8;                \
    CPA16(sb + sd0,         Ah + ga0);  CPA16(sb + sd1,         Ah + ga1);     \
    CPA16(sb + 10240 + sd0, Al + ga0);  CPA16(sb + 10240 + sd1, Al + ga1);     \
    CPA16(sb + 20480 + sd0, Bh + gb0);  CPA16(sb + 20480 + sd1, Bh + gb1);     \
    CPA16(sb + 30720 + sd0, Bl + gb0);  CPA16(sb + 30720 + sd1, Bl + gb1);     \
    CPA_COMMIT();                                                              \
} while (0)

    ISSUE_CHUNK(0, 0);
    ISSUE_CHUNK(1, 1);
#pragma unroll 1
    for (int c = 0; c < 8; c++) {
        if (c < 7) { CPA_WAIT(1); } else { CPA_WAIT(0); }
        __syncthreads();
        unsigned stage = smb + (c & 1) * STG_STRIDE;
#pragma unroll
        for (int ks = 0; ks < 2; ks++) {
            unsigned kb = ks * 32;
            unsigned bhf[4][2], blf[4][2];
#pragma unroll
            for (int nt = 0; nt < 4; nt++) {
                unsigned ba = stage + 20480 + (unsigned)(wn + nt * 8 + g) * 80 + t * 4 + kb;
                bhf[nt][0] = lds32(ba);          bhf[nt][1] = lds32(ba + 16);
                blf[nt][0] = lds32(ba + 10240);  blf[nt][1] = lds32(ba + 10256);
            }
#pragma unroll
            for (int mt = 0; mt < 4; mt++) {
                unsigned aa = stage + (unsigned)(wm + mt * 16 + g) * 80 + t * 4 + kb;
                unsigned ahf[4], alf[4];
                ahf[0] = lds32(aa);        ahf[1] = lds32(aa + 640);
                ahf[2] = lds32(aa + 16);   ahf[3] = lds32(aa + 656);
                alf[0] = lds32(aa + 10240);        alf[1] = lds32(aa + 10880);
                alf[2] = lds32(aa + 10256);        alf[3] = lds32(aa + 10896);
#pragma unroll
                for (int nt = 0; nt < 4; nt++) {
                    mma16816(acc[mt][nt], ahf, bhf[nt]);
                    mma16816(acc[mt][nt], ahf, blf[nt]);
                    mma16816(acc[mt][nt], alf, bhf[nt]);
                }
            }
        }
        __syncthreads();
        if (c < 6) ISSUE_CHUNK(c + 2, c & 1);
    }
#undef ISSUE_CHUNK

    if (which == 1) {
#pragma unroll
        for (int nt = 0; nt < 4; nt++) {
            int col = o0 + wn + nt * 8 + t * 2;
            float b0 = __ldg(&bias[col]), b1 = __ldg(&bias[col + 1]);
#pragma unroll
            for (int mt = 0; mt < 4; mt++) {
                int row = n0 + wm + mt * 16 + g;
                float* p = g_proj + ((size_t)b * NW + row) * 256 + col;
                *(float2*)p = make_float2(acc[mt][nt][0] + b0, acc[mt][nt][1] + b1);
                *(float2*)(p + (size_t)8 * 256) =
                    make_float2(acc[mt][nt][2] + b0, acc[mt][nt][3] + b1);
            }
        }
    } else {
        // qk token-major writes + V^T staged via smem (pitch 136 ushort, 16B rows)
        unsigned short* vtb_h = (unsigned short*)sm;            // [128][136]
        unsigned short* vtb_l = (unsigned short*)(sm + 34816);  // [128][136]
#pragma unroll
        for (int nt = 0; nt < 4; nt++) {
            int colL = wn + nt * 8 + t * 2;
            int col = o0 + colL;
#pragma unroll
            for (int mt = 0; mt < 4; mt++) {
#pragma unroll
                for (int rr = 0; rr < 2; rr++) {
                    int rl = wm + mt * 16 + g + rr * 8;
                    float v0 = acc[mt][nt][rr * 2], v1 = acc[mt][nt][rr * 2 + 1];
                    unsigned hpair = pack_bf16x2(v0, v1);
                    float h0f = __uint_as_float(hpair << 16);
                    float h1f = __uint_as_float(hpair & 0xffff0000u);
                    unsigned lpair = pack_bf16x2(v0 - h0f, v1 - h1f);
                    size_t oo = ((size_t)b * NW + n0 + rl) * 768 + col;
                    *(unsigned*)&g_qkh[oo] = hpair;
                    *(unsigned*)&g_qkl[oo] = lpair;
                    vtb_h[colL * 136 + rl] = (unsigned short)(hpair & 0xffffu);
                    vtb_h[(colL + 1) * 136 + rl] = (unsigned short)(hpair >> 16);
                    vtb_l[colL * 136 + rl] = (unsigned short)(lpair & 0xffffu);
                    vtb_l[(colL + 1) * 136 + rl] = (unsigned short)(lpair >> 16);
                }
            }
        }
        __syncthreads();
        // coalesced V^T writes: rows that are V columns (col%96 >= 64)
#pragma unroll
        for (int it = 0; it < 8; it++) {
            int idx = tid + it * 256;
            int row = idx >> 4, seg = idx & 15;
            int col = o0 + row;
            int cm = col % 96, hh = col / 96;
            if (cm >= 64) {
                size_t vb = (((size_t)b * 8 + hh) * 32 + (cm - 64)) * 1024 + n0 + seg * 8;
                *(uint4*)&g_vTh[vb] = *(uint4*)&vtb_h[row * 136 + seg * 8];
                *(uint4*)&g_vTl[vb] = *(uint4*)&vtb_l[row * 136 + seg * 8];
            }
        }
    }
}

// ---------------- kernel 5: flash-MMA attention, cp.async double-buffered ---
#define ATT_STAGE 42240
#define ATT_SMEM (20480 + 2 * ATT_STAGE)
__global__ void __launch_bounds__(256) attn_mma() {
    extern __shared__ __align__(16) char asm_[];
    int qb = blockIdx.x, h = blockIdx.y, b = blockIdx.z;
    int m0 = qb * 128;
    int tid = threadIdx.x, w = tid >> 5, lane = tid & 31, g = lane >> 2, t = lane & 3;
    unsigned sb = smem_u32(asm_);
    const unsigned Qh = sb, Ql = sb + 10240;
    const float hs = 0.17677669529663687f;

    {
        const __nv_bfloat16* qh = g_qkh + ((size_t)b * NW + m0) * 768 + h * 96;
        const __nv_bfloat16* ql = g_qkl + ((size_t)b * NW + m0) * 768 + h * 96;
#pragma unroll
        for (int it = 0; it < 2; it++) {
            int idx = tid + it * 256;
            int row = idx >> 2, q = idx & 3;
            uint4 vh = *(const uint4*)(qh + (size_t)row * 768 + q * 8);
            uint4 vl = *(const uint4*)(ql + (size_t)row * 768 + q * 8);
            *(uint4*)(asm_ + row * 80 + q * 16) = vh;
            *(uint4*)(asm_ + 10240 + row * 80 + q * 16) = vl;
        }
    }
#pragma unroll
    for (int s = 0; s < 2; s++)
        for (int idx = tid; idx < 544; idx += 256) {
            int row = 32 + idx / 68, wd = idx % 68;
            ((unsigned*)(asm_ + 20480 + s * ATT_STAGE + 20480))[row * 68 + wd] =
                (row == 32 && wd < 64) ? 0x3F803F80u : 0u;
            ((unsigned*)(asm_ + 20480 + s * ATT_STAGE + 31360))[row * 68 + wd] = 0u;
        }
    __syncthreads();
    unsigned ah[2][4], al[2][4];
    {
        unsigned qa = Qh + (unsigned)(w * 16 + g) * 80 + t * 4;
        unsigned qa_l = Ql + (unsigned)(w * 16 + g) * 80 + t * 4;
#pragma unroll
        for (int kt2 = 0; kt2 < 2; kt2++) {
            unsigned o = kt2 * 32;
            ah[kt2][0] = lds32(qa + o);       ah[kt2][1] = lds32(qa + o + 640);
            ah[kt2][2] = lds32(qa + o + 16);  ah[kt2][3] = lds32(qa + o + 656);
            al[kt2][0] = lds32(qa_l + o);      al[kt2][1] = lds32(qa_l + o + 640);
            al[kt2][2] = lds32(qa_l + o + 16); al[kt2][3] = lds32(qa_l + o + 656);
        }
    }

    float O[5][4];
#pragma unroll
    for (int v = 0; v < 5; v++)
#pragma unroll
        for (int j = 0; j < 4; j++) O[v][j] = 0.f;

    int krow = tid >> 2, kq = tid & 3;
    const __nv_bfloat16* khb = g_qkh + (size_t)b * NW * 768 + h * 96 + 32;
    const __nv_bfloat16* klb = g_qkl + (size_t)b * NW * 768 + h * 96 + 32;
    int vd = tid >> 3, vseg = tid & 7;
    const unsigned short* vthb = g_vTh + (((size_t)b * 8 + h) * 32 + vd) * 1024 + vseg * 16;
    const unsigned short* vtlb = g_vTl + (((size_t)b * 8 + h) * 32 + vd) * 1024 + vseg * 16;

#define ATT_ISSUE(kt, s) do {                                                  \
    size_t nn = (size_t)(kt) * 128;                                            \
    unsigned ks_ = sb + 20480 + (s) * ATT_STAGE;                               \
    CPA16(ks_ + krow * 80 + kq * 16,               khb + (nn + krow) * 768 + kq * 8);      \
    CPA16(ks_ + 10240 + krow * 80 + kq * 16,       klb + (nn + krow) * 768 + kq * 8);      \
    CPA16(ks_ + (krow + 64) * 80 + kq * 16,        khb + (nn + krow + 64) * 768 + kq * 8); \
    CPA16(ks_ + 10240 + (krow + 64) * 80 + kq * 16, klb + (nn + krow + 64) * 768 + kq * 8);\
    CPA16(ks_ + 20480 + vd * 272 + vseg * 32,      vthb + nn);                 \
    CPA16(ks_ + 20480 + vd * 272 + vseg * 32 + 16, vthb + nn + 8);             \
    CPA16(ks_ + 31360 + vd * 272 + vseg * 32,      vtlb + nn);                 \
    CPA16(ks_ + 31360 + vd * 272 + vseg * 32 + 16, vtlb + nn + 8);             \
    CPA_COMMIT();                                                              \
} while (0)

    ATT_ISSUE(0, 0);
#pragma unroll 1
    for (int kt = 0; kt < 8; kt++) {
        if (kt < 7) { ATT_ISSUE(kt + 1, (kt + 1) & 1); CPA_WAIT(1); }
        else        { CPA_WAIT(0); }
        __syncthreads();
        unsigned ksb = sb + 20480 + (kt & 1) * ATT_STAGE;
        unsigned KhS = ksb, KlS = ksb + 10240, VhS = ksb + 20480, VlS = ksb + 31360;

        unsigned pa_h[8][4], pa_l[8][4];
#pragma unroll
        for (int j = 0; j < 16; j++) {
            float s[4] = {0.f, 0.f, 0.f, 0.f};
            unsigned kbase = KhS + (unsigned)(j * 8 + g) * 80 + t * 4;
            unsigned kbase_l = KlS + (unsigned)(j * 8 + g) * 80 + t * 4;
#pragma unroll
            for (int kt2 = 0; kt2 < 2; kt2++) {
                unsigned o = kt2 * 32;
                unsigned bh[2] = {lds32(kbase + o), lds32(kbase + o + 16)};
                unsigned bl[2] = {lds32(kbase_l + o), lds32(kbase_l + o + 16)};
                mma16816(s, ah[kt2], bh);
                mma16816(s, ah[kt2], bl);
                mma16816(s, al[kt2], bh);
            }
            float p0 = __expf(s[0] * hs), p1 = __expf(s[1] * hs);
            float p2 = __expf(s[2] * hs), p3 = __expf(s[3] * hs);
            unsigned h01 = pack_bf16x2(p0, p1);
            unsigned h23 = pack_bf16x2(p2, p3);
            unsigned l01 = pack_bf16x2(p0 - __uint_as_float(h01 << 16),
                                       p1 - __uint_as_float(h01 & 0xffff0000u));
            unsigned l23 = pack_bf16x2(p2 - __uint_as_float(h23 << 16),
                                       p3 - __uint_as_float(h23 & 0xffff0000u));
            int kk = j >> 1, hf = (j & 1) * 2;
            pa_h[kk][hf] = h01; pa_h[kk][hf + 1] = h23;
            pa_l[kk][hf] = l01; pa_l[kk][hf + 1] = l23;
        }
#pragma unroll
        for (int v = 0; v < 5; v++) {
            unsigned vb = VhS + (unsigned)(v * 8 + g) * 272 + t * 4;
            unsigned vb_l = VlS + (unsigned)(v * 8 + g) * 272 + t * 4;
#pragma unroll
            for (int kk = 0; kk < 8; kk++) {
                unsigned o = kk * 32;
                unsigned bh[2] = {lds32(vb + o), lds32(vb + o + 16)};
                unsigned bl[2] = {lds32(vb_l + o), lds32(vb_l + o + 16)};
                mma16816(O[v], pa_h[kk], bh);
                mma16816(O[v], pa_h[kk], bl);
                mma16816(O[v], pa_l[kk], bh);
            }
        }
        __syncthreads();
    }
#undef ATT_ISSUE
    float lg = __shfl_sync(0xffffffffu, O[4][0], lane & 28);
    float lg8 = __shfl_sync(0xffffffffu, O[4][2], lane & 28);
    float inv = 1.f / lg, inv8 = 1.f / lg8;
    size_t ob = ((size_t)b * NW + m0 + w * 16 + g) * 256 + h * 32;
    size_t ob8 = ob + (size_t)8 * 256;
#pragma unroll
    for (int v = 0; v < 4; v++) {
        int d = v * 8 + t * 2;
        float x0 = O[v][0] * inv, x1 = O[v][1] * inv;
        float x2 = O[v][2] * inv8, x3 = O[v][3] * inv8;
        unsigned hp0 = pack_bf16x2(x0, x1);
        unsigned lp0 = pack_bf16x2(x0 - __uint_as_float(hp0 << 16),
                                   x1 - __uint_as_float(hp0 & 0xffff0000u));
        unsigned hp1 = pack_bf16x2(x2, x3);
        unsigned lp1 = pack_bf16x2(x2 - __uint_as_float(hp1 << 16),
                                   x3 - __uint_as_float(hp1 & 0xffff0000u));
        *(unsigned*)&g_aoh[ob + d] = hp0;
        *(unsigned*)&g_aol[ob + d] = lp0;
        *(unsigned*)&g_aoh[ob8 + d] = hp1;
        *(unsigned*)&g_aol[ob8 + d] = lp1;
    }
}

// ---------------- kernel 7: scatter, c-split across blockIdx.z --------------
__global__ void scatter_kernel(float* __restrict__ out) {
    __shared__ float aff_s[32 * 144];
    __shared__ float r_s[3 * 34 * 33];
    int Y = blockIdx.x, b = blockIdx.y;
    int cbase = blockIdx.z * 64;      // 64-channel slice per block
    int tid = threadIdx.x;
    int X = tid >> 2, px = tid & 3;
    const float* ab = g_aff + ((size_t)b * NW + Y * 32) * 144;
    for (int idx = tid; idx < 4608; idx += 128) aff_s[idx] = ab[idx];
    for (int idx = tid; idx < 3 * 34 * 33; idx += 128) r_s[idx] = 0.f;
    __syncthreads();
    float a[4][9];
#pragma unroll
    for (int py = 0; py < 4; py++)
#pragma unroll
        for (int i = 0; i < 9; i++)
            a[py][i] = aff_s[X * 144 + (py * 4 + px) * 9 + i];

#pragma unroll
    for (int cc0 = 0; cc0 < 64; cc0 += 32) {
        int c0 = cbase + cc0;
        __syncthreads();
        for (int idx = tid; idx < 3 * 32 * 32; idx += 128) {
            int dy = idx >> 10;
            int rem = idx & 1023;
            int Xl = rem >> 5, cc = rem & 31;
            int ny = Y + dy - 1;
            if ((unsigned)ny < 32u)
                r_s[((dy * 34) + Xl + 1) * 33 + cc] =
                    g_proj[((size_t)b * NW + ny * 32 + Xl) * Cv + c0 + cc];
        }
        __syncthreads();
#pragma unroll 4
        for (int c = 0; c < 32; c++) {
            float r[9];
#pragma unroll
            for (int i = 0; i < 9; i++) {
                int dy = i / 3, dx = i % 3;
                r[i] = r_s[((dy * 34) + X + dx) * 33 + c];
            }
            size_t obase = ((size_t)b * 256 + c0 + c) * 16384 +
                           (size_t)(Y * 4) * 128 + tid;
#pragma unroll
            for (int py = 0; py < 4; py++) {
                float v = 0.f;
#pragma unroll
                for (int i = 0; i < 9; i++) v = fmaf(r[i], a[py][i], v);
                out[obase + (size_t)py * 128] = v;
            }
        }
    }
}

// ---------------- launch ----------------
extern "C" void kernel_launch(void* const* d_in, const int* in_sizes, int n_in,
                              void* d_out, int out_size) {
    const float* x = nullptr; const float* qkv_w = nullptr;
    const float* proj_w = nullptr; const float* proj_b = nullptr;
    for (int i = 0; i < n_in; i++) {
        int s = in_sizes[i];
        if (s == 8 * 16384 * 256) x = (const float*)d_in[i];
        else if (s == 768 * 256)  qkv_w = (const float*)d_in[i];
        else if (s == 256 * 256)  proj_w = (const float*)d_in[i];
        else if (s == 256)        proj_b = (const float*)d_in[i];
    }
    float* out = (float*)d_out;

    const int DSMEM = 2 * STG_STRIDE;
    cudaFuncSetAttribute(gemm_mma, cudaFuncAttributeMaxDynamicSharedMemorySize, DSMEM);
    cudaFuncSetAttribute(attn_mma, cudaFuncAttributeMaxDynamicSharedMemorySize, ATT_SMEM);

    pool_kernel<<<dim3(256, 8), 256>>>(x);
    conv_w<<<768, 256>>>(qkv_w, proj_w);
    aff_kernel<<<dim3(1024, 8), 256>>>(x);
    fold_kernel<<<dim3(256, 8), 256>>>();
    gemm_mma<<<dim3(8, 6, 8), 256, DSMEM>>>(0, nullptr, 768);
    attn_mma<<<dim3(8, 8, 8), 256, ATT_SMEM>>>();
    gemm_mma<<<dim3(8, 2, 8), 256, DSMEM>>>(1, proj_b, 256);
    scatter_kernel<<<dim3(32, 8, 4), 128>>>(out);
}

// round 17
// speedup vs baseline: 1.0877x; 1.0116x over previous
#include <cuda_runtime.h>
#include <cuda_bf16.h>
#include <math.h>
#include <stdint.h>

#define Bv 8
#define Cv 256
#define NW 1024      // 32*32 super tokens
#define NHEADS 8
#define HD 32

// ---------------- scratch (static device memory; no allocs) ----------------
__device__ float g_wf[Bv * NW * Cv];                 // (b, t, c)
__device__ float g_aff[Bv * NW * 16 * 9];            // (b, t, p, i)
__device__ float g_wf2raw[(size_t)Bv * NW * 9 * Cv]; // (b, t, i, c)
__device__ float g_affsumraw[Bv * NW * 9];           // (b, t, i)
__device__ __nv_bfloat16 g_wf2h[Bv * NW * Cv];       // tokens hi (b, t, c)
__device__ __nv_bfloat16 g_wf2l[Bv * NW * Cv];       // tokens lo
__device__ __nv_bfloat16 g_qkvwh[768 * 256];         // qkv weight hi (o,k)
__device__ __nv_bfloat16 g_qkvwl[768 * 256];
__device__ __nv_bfloat16 g_pwh[256 * 256];           // proj weight hi (o,k)
__device__ __nv_bfloat16 g_pwl[256 * 256];
__device__ __nv_bfloat16 g_qkh[(size_t)Bv * NW * 768];  // qkv out hi (b, n, o)
__device__ __nv_bfloat16 g_qkl[(size_t)Bv * NW * 768];  // qkv out lo
__device__ unsigned short g_vTh[(size_t)Bv * 8 * 32 * 1024]; // V^T hi (b,h,d,n)
__device__ unsigned short g_vTl[(size_t)Bv * 8 * 32 * 1024]; // V^T lo
__device__ __nv_bfloat16 g_aoh[Bv * NW * Cv];        // attn out hi (b, n, c)
__device__ __nv_bfloat16 g_aol[Bv * NW * Cv];        // attn out lo
__device__ float g_proj[(size_t)Bv * NW * Cv];       // (b, n, o)

// ---------------- f32x2 packed-math helpers (sm_103a) ----------------
typedef unsigned long long u64;
__device__ __forceinline__ u64 f2_dup(float a) {
    u64 d; asm("mov.b64 %0, {%1, %1};" : "=l"(d) : "f"(a)); return d;
}
__device__ __forceinline__ void f2_unpack(float& a, float& b, u64 d) {
    asm("mov.b64 {%0, %1}, %2;" : "=f"(a), "=f"(b) : "l"(d));
}
__device__ __forceinline__ void fma2(u64& c, u64 a, u64 b) {
    asm("fma.rn.f32x2 %0, %1, %2, %0;" : "+l"(c) : "l"(a), "l"(b));
}
__device__ __forceinline__ u64 lds64(unsigned saddr) {
    u64 v;
    asm volatile("ld.shared.b64 %0, [%1];" : "=l"(v) : "r"(saddr));
    return v;
}
__device__ __forceinline__ unsigned lds32(unsigned saddr) {
    unsigned v;
    asm volatile("ld.shared.b32 %0, [%1];" : "=r"(v) : "r"(saddr));
    return v;
}
__device__ __forceinline__ unsigned smem_u32(const void* p) {
    unsigned a;
    asm("{ .reg .u64 t; cvta.to.shared.u64 t, %1; cvt.u32.u64 %0, t; }" : "=r"(a) : "l"(p));
    return a;
}
// pack: low half = lo, high half = hi (PTX: first src -> upper)
__device__ __forceinline__ unsigned pack_bf16x2(float lo, float hi) {
    unsigned d;
    asm("cvt.rn.bf16x2.f32 %0, %1, %2;" : "=r"(d) : "f"(hi), "f"(lo));
    return d;
}

// ---------------- mma.sync + cp.async helpers (portable sm_80+) -------------
__device__ __forceinline__ void mma16816(float* c, const unsigned* a, const unsigned* b) {
    asm volatile(
        "mma.sync.aligned.m16n8k16.row.col.f32.bf16.bf16.f32 "
        "{%0,%1,%2,%3}, {%4,%5,%6,%7}, {%8,%9}, {%0,%1,%2,%3};"
        : "+f"(c[0]), "+f"(c[1]), "+f"(c[2]), "+f"(c[3])
        : "r"(a[0]), "r"(a[1]), "r"(a[2]), "r"(a[3]), "r"(b[0]), "r"(b[1]));
}
#define CPA16(dst, src) \
    asm volatile("cp.async.ca.shared.global [%0], [%1], 16;" :: "r"(dst), "l"(src))
#define CPA_COMMIT() asm volatile("cp.async.commit_group;" ::: "memory")
#define CPA_WAIT(n)  asm volatile("cp.async.wait_group %0;" :: "n"(n) : "memory")

// ---------------- kernel 1: 4x4 average pool -> wf (float4) ----------------
__global__ void pool_kernel(const float* __restrict__ x) {
    int b = blockIdx.y;
    int t = blockIdx.x * 4 + (threadIdx.x >> 6);
    int c4 = (threadIdx.x & 63) * 4;
    int Y = t >> 5, X = t & 31;
    const float* xb = x + (size_t)b * 16384 * 256;
    float4 s = make_float4(0.f, 0.f, 0.f, 0.f);
#pragma unroll
    for (int py = 0; py < 4; py++)
#pragma unroll
        for (int px = 0; px < 4; px++) {
            int n = (Y * 4 + py) * 128 + X * 4 + px;
            float4 v = *(const float4*)&xb[(size_t)n * 256 + c4];
            s.x += v.x; s.y += v.y; s.z += v.z; s.w += v.w;
        }
    s.x *= (1.f / 16.f); s.y *= (1.f / 16.f); s.z *= (1.f / 16.f); s.w *= (1.f / 16.f);
    *(float4*)&g_wf[((size_t)b * NW + t) * Cv + c4] = s;
}

// ---------------- weight conversion: fp32 -> bf16 hi/lo (both weights) ------
__global__ void conv_w(const float* __restrict__ qw, const float* __restrict__ pw) {
    int i = blockIdx.x * 256 + threadIdx.x;
    if (i < 768 * 256) {
        float x = qw[i];
        __nv_bfloat16 h = __float2bfloat16(x);
        g_qkvwh[i] = h;
        g_qkvwl[i] = __float2bfloat16(x - __bfloat162float(h));
    }
    if (i < 256 * 256) {
        float x = pw[i];
        __nv_bfloat16 h = __float2bfloat16(x);
        g_pwh[i] = h;
        g_pwl[i] = __float2bfloat16(x - __bfloat162float(h));
    }
}

// ---------------- kernel 2: affinity softmax + wf2 window partials ----------
// Dot phase: warp owns 2 p-rows; pix register-cached; paired-half reduction.
__global__ void aff_kernel(const float* __restrict__ x) {
    __shared__ float pix[16][256];
    __shared__ float wfu[9][256];
    __shared__ float lg[16][9];
    __shared__ float affs[16][9];
    int b = blockIdx.y, t = blockIdx.x, tid = threadIdx.x;
    int Y = t >> 5, X = t & 31;
    const float* xb = x + (size_t)b * 16384 * 256;
    {
        int c4 = (tid & 63) * 4;
#pragma unroll
        for (int pp = 0; pp < 4; pp++) {
            int p = pp * 4 + (tid >> 6);
            int n = (Y * 4 + (p >> 2)) * 128 + X * 4 + (p & 3);
            *(float4*)&pix[p][c4] = *(const float4*)&xb[(size_t)n * 256 + c4];
        }
#pragma unroll
        for (int ii = 0; ii < 3; ii++) {
            int i = ii * 4 + (tid >> 6);
            if (i < 9) {
                int ny = Y + (i / 3) - 1, nx = X + (i % 3) - 1;
                float4 v = make_float4(0.f, 0.f, 0.f, 0.f);
                if ((unsigned)ny < 32u && (unsigned)nx < 32u)
                    v = *(const float4*)&g_wf[((size_t)b * NW + ny * 32 + nx) * Cv + c4];
                *(float4*)&wfu[i][c4] = v;
            }
        }
    }
    __syncthreads();
    int warp = tid >> 5, lane = tid & 31;
    {
        int p0 = warp * 2, p1 = p0 + 1;
        unsigned pixb = smem_u32(&pix[0][0]) + (unsigned)lane * 8 + (unsigned)p0 * 1024;
        unsigned wfub = smem_u32(&wfu[0][0]) + (unsigned)lane * 8;
        u64 pr0[4], pr1[4];
#pragma unroll
        for (int k = 0; k < 4; k++) {
            pr0[k] = lds64(pixb + k * 256);
            pr1[k] = lds64(pixb + 1024 + k * 256);
        }
#pragma unroll
        for (int i = 0; i < 9; i++) {
            u64 s0 = 0ull, s1 = 0ull;
#pragma unroll
            for (int k = 0; k < 4; k++) {
                u64 wf = lds64(wfub + i * 1024 + k * 256);
                fma2(s0, pr0[k], wf);
                fma2(s1, pr1[k], wf);
            }
            float a0, c0, a1, c1;
            f2_unpack(a0, c0, s0);
            f2_unpack(a1, c1, s1);
            float v0 = a0 + c0, v1 = a1 + c1;
            float td = __shfl_down_sync(0xffffffffu, v0, 16);
            float tu = __shfl_up_sync(0xffffffffu, v1, 16);
            float wv = (lane < 16) ? (v0 + td) : (v1 + tu);
#pragma unroll
            for (int off = 8; off; off >>= 1)
                wv += __shfl_down_sync(0xffffffffu, wv, off);
            if (lane == 0)  lg[p0][i] = wv * 0.0625f;
            if (lane == 16) lg[p1][i] = wv * 0.0625f;
        }
    }
    __syncthreads();
    if (tid < 16) {
        float m = -1e30f;
#pragma unroll
        for (int i = 0; i < 9; i++) m = fmaxf(m, lg[tid][i]);
        float e[9], sum = 0.f;
#pragma unroll
        for (int i = 0; i < 9; i++) { e[i] = __expf(lg[tid][i] - m); sum += e[i]; }
        float inv = 1.f / sum;
#pragma unroll
        for (int i = 0; i < 9; i++) affs[tid][i] = e[i] * inv;
    }
    __syncthreads();
    if (tid < 144)
        g_aff[((size_t)b * NW + t) * 144 + tid] = affs[tid / 9][tid % 9];
    if (tid >= 160 && tid < 169) {
        int i = tid - 160;
        float s = 0.f;
#pragma unroll
        for (int p = 0; p < 16; p++) s += affs[p][i];
        g_affsumraw[((size_t)b * NW + t) * 9 + i] = s;
    }
    float acc[9];
#pragma unroll
    for (int i = 0; i < 9; i++) acc[i] = 0.f;
#pragma unroll
    for (int p = 0; p < 16; p++) {
        float v = pix[p][tid];
#pragma unroll
        for (int i = 0; i < 9; i++) acc[i] = fmaf(v, affs[p][i], acc[i]);
    }
    size_t base = ((size_t)b * NW + t) * 9 * Cv;
#pragma unroll
    for (int i = 0; i < 9; i++) g_wf2raw[base + (size_t)i * Cv + tid] = acc[i];
}

// ---------------- kernel 3: fold-gather + normalize -> bf16 hi/lo -----------
__global__ void fold_kernel() {
    int b = blockIdx.y;
    int t = blockIdx.x * 4 + (threadIdx.x >> 6);
    int c = (threadIdx.x & 63) * 4;
    int Y = t >> 5, X = t & 31;
    float4 acc = make_float4(0.f, 0.f, 0.f, 0.f);
    float asum = 0.f;
#pragma unroll
    for (int i = 0; i < 9; i++) {
        int ny = Y - ((i / 3) - 1), nx = X - ((i % 3) - 1);
        if ((unsigned)ny < 32u && (unsigned)nx < 32u) {
            size_t nb = (size_t)b * NW + ny * 32 + nx;
            float4 v = *(const float4*)&g_wf2raw[(nb * 9 + i) * Cv + c];
            acc.x += v.x; acc.y += v.y; acc.z += v.z; acc.w += v.w;
            asum += g_affsumraw[nb * 9 + i];
        }
    }
    float inv = 1.f / (asum + 1e-12f);
    float f[4] = {acc.x * inv, acc.y * inv, acc.z * inv, acc.w * inv};
    size_t off = ((size_t)b * NW + t) * Cv + c;
    __nv_bfloat162 h01, h23, l01, l23;
    h01.x = __float2bfloat16(f[0]); h01.y = __float2bfloat16(f[1]);
    h23.x = __float2bfloat16(f[2]); h23.y = __float2bfloat16(f[3]);
    l01.x = __float2bfloat16(f[0] - __bfloat162float(h01.x));
    l01.y = __float2bfloat16(f[1] - __bfloat162float(h01.y));
    l23.x = __float2bfloat16(f[2] - __bfloat162float(h23.x));
    l23.y = __float2bfloat16(f[3] - __bfloat162float(h23.y));
    *(__nv_bfloat162*)&g_wf2h[off] = h01;
    *(__nv_bfloat162*)&g_wf2h[off + 2] = h23;
    *(__nv_bfloat162*)&g_wf2l[off] = l01;
    *(__nv_bfloat162*)&g_wf2l[off + 2] = l23;
}

// ---------------- GEMM via mma.sync bf16 (3-term hi/lo split) ---------------
// which==0 (qkv): out bf16 hi/lo token-major + smem-transposed coalesced V^T.
// which==1 (proj): f32+bias.
#define STG_STRIDE 40960
__global__ void __launch_bounds__(256) gemm_mma(int which,
                                                const float* __restrict__ bias,
                                                int outStride) {
    extern __shared__ __align__(16) char sm[];
    int b = blockIdx.z;
    int n0 = blockIdx.x * 128, o0 = blockIdx.y * 128;
    int tid = threadIdx.x;
    int w = tid >> 5, lane = tid & 31, g = lane >> 2, t = lane & 3;
    int wm = (w >> 2) * 64, wn = (w & 3) * 32;

    const __nv_bfloat16* Ah = (which == 0 ? g_wf2h : g_aoh) + (size_t)b * NW * Cv;
    const __nv_bfloat16* Al = (which == 0 ? g_wf2l : g_aol) + (size_t)b * NW * Cv;
    const __nv_bfloat16* Bh = (which == 0 ? g_qkvwh : g_pwh);
    const __nv_bfloat16* Bl = (which == 0 ? g_qkvwl : g_pwl);

    unsigned smb = smem_u32(sm);
    int lr0 = tid >> 2, lq = tid & 3;
    int lr1 = lr0 + 64;
    unsigned sd0 = lr0 * 80 + lq * 16;
    unsigned sd1 = lr1 * 80 + lq * 16;

    float acc[4][4][4];
#pragma unroll
    for (int mt = 0; mt < 4; mt++)
#pragma unroll
        for (int nt = 0; nt < 4; nt++)
#pragma unroll
            for (int j = 0; j < 4; j++) acc[mt][nt][j] = 0.f;

#define ISSUE_CHUNK(kc, s) do {                                                \
    unsigned sb = smb + (s) * STG_STRIDE;                                      \
    size_t ga0 = (size_t)(n0 + lr0) * 256 + (kc) * 32 + lq * 8;                \
    size_t ga1 = (size_t)(n0 + lr1) * 256 + (kc) * 32 + lq * 8;                \
    size_t gb0 = (size_t)(o0 + lr0) * 256 + (kc) * 32 + lq * 8;                \
    size_t gb1 = (size_t)(o0 + lr1) * 256 + (kc) * 32 + lq * 8;                \
    CPA16(sb + sd0,         Ah + ga0);  CPA16(sb + sd1,         Ah + ga1);     \
    CPA16(sb + 10240 + sd0, Al + ga0);  CPA16(sb + 10240 + sd1, Al + ga1);     \
    CPA16(sb + 20480 + sd0, Bh + gb0);  CPA16(sb + 20480 + sd1, Bh + gb1);     \
    CPA16(sb + 30720 + sd0, Bl + gb0);  CPA16(sb + 30720 + sd1, Bl + gb1);     \
    CPA_COMMIT();                                                              \
} while (0)

    ISSUE_CHUNK(0, 0);
    ISSUE_CHUNK(1, 1);
#pragma unroll 1
    for (int c = 0; c < 8; c++) {
        if (c < 7) { CPA_WAIT(1); } else { CPA_WAIT(0); }
        __syncthreads();
        unsigned stage = smb + (c & 1) * STG_STRIDE;
#pragma unroll
        for (int ks = 0; ks < 2; ks++) {
            unsigned kb = ks * 32;
            unsigned bhf[4][2], blf[4][2];
#pragma unroll
            for (int nt = 0; nt < 4; nt++) {
                unsigned ba = stage + 20480 + (unsigned)(wn + nt * 8 + g) * 80 + t * 4 + kb;
                bhf[nt][0] = lds32(ba);          bhf[nt][1] = lds32(ba + 16);
                blf[nt][0] = lds32(ba + 10240);  blf[nt][1] = lds32(ba + 10256);
            }
#pragma unroll
            for (int mt = 0; mt < 4; mt++) {
                unsigned aa = stage + (unsigned)(wm + mt * 16 + g) * 80 + t * 4 + kb;
                unsigned ahf[4], alf[4];
                ahf[0] = lds32(aa);        ahf[1] = lds32(aa + 640);
                ahf[2] = lds32(aa + 16);   ahf[3] = lds32(aa + 656);
                alf[0] = lds32(aa + 10240);        alf[1] = lds32(aa + 10880);
                alf[2] = lds32(aa + 10256);        alf[3] = lds32(aa + 10896);
#pragma unroll
                for (int nt = 0; nt < 4; nt++) {
                    mma16816(acc[mt][nt], ahf, bhf[nt]);
                    mma16816(acc[mt][nt], ahf, blf[nt]);
                    mma16816(acc[mt][nt], alf, bhf[nt]);
                }
            }
        }
        __syncthreads();
        if (c < 6) ISSUE_CHUNK(c + 2, c & 1);
    }
#undef ISSUE_CHUNK

    if (which == 1) {
#pragma unroll
        for (int nt = 0; nt < 4; nt++) {
            int col = o0 + wn + nt * 8 + t * 2;
            float b0 = __ldg(&bias[col]), b1 = __ldg(&bias[col + 1]);
#pragma unroll
            for (int mt = 0; mt < 4; mt++) {
                int row = n0 + wm + mt * 16 + g;
                float* p = g_proj + ((size_t)b * NW + row) * 256 + col;
                *(float2*)p = make_float2(acc[mt][nt][0] + b0, acc[mt][nt][1] + b1);
                *(float2*)(p + (size_t)8 * 256) =
                    make_float2(acc[mt][nt][2] + b0, acc[mt][nt][3] + b1);
            }
        }
    } else {
        // qk token-major writes + V^T staged via smem (pitch 136 ushort, 16B rows)
        unsigned short* vtb_h = (unsigned short*)sm;            // [128][136]
        unsigned short* vtb_l = (unsigned short*)(sm + 34816);  // [128][136]
#pragma unroll
        for (int nt = 0; nt < 4; nt++) {
            int colL = wn + nt * 8 + t * 2;
            int col = o0 + colL;
#pragma unroll
            for (int mt = 0; mt < 4; mt++) {
#pragma unroll
                for (int rr = 0; rr < 2; rr++) {
                    int rl = wm + mt * 16 + g + rr * 8;
                    float v0 = acc[mt][nt][rr * 2], v1 = acc[mt][nt][rr * 2 + 1];
                    unsigned hpair = pack_bf16x2(v0, v1);
                    float h0f = __uint_as_float(hpair << 16);
                    float h1f = __uint_as_float(hpair & 0xffff0000u);
                    unsigned lpair = pack_bf16x2(v0 - h0f, v1 - h1f);
                    size_t oo = ((size_t)b * NW + n0 + rl) * 768 + col;
                    *(unsigned*)&g_qkh[oo] = hpair;
                    *(unsigned*)&g_qkl[oo] = lpair;
                    vtb_h[colL * 136 + rl] = (unsigned short)(hpair & 0xffffu);
                    vtb_h[(colL + 1) * 136 + rl] = (unsigned short)(hpair >> 16);
                    vtb_l[colL * 136 + rl] = (unsigned short)(lpair & 0xffffu);
                    vtb_l[(colL + 1) * 136 + rl] = (unsigned short)(lpair >> 16);
                }
            }
        }
        __syncthreads();
        // coalesced V^T writes: rows that are V columns (col%96 >= 64)
#pragma unroll
        for (int it = 0; it < 8; it++) {
            int idx = tid + it * 256;
            int row = idx >> 4, seg = idx & 15;
            int col = o0 + row;
            int cm = col % 96, hh = col / 96;
            if (cm >= 64) {
                size_t vb = (((size_t)b * 8 + hh) * 32 + (cm - 64)) * 1024 + n0 + seg * 8;
                *(uint4*)&g_vTh[vb] = *(uint4*)&vtb_h[row * 136 + seg * 8];
                *(uint4*)&g_vTl[vb] = *(uint4*)&vtb_l[row * 136 + seg * 8];
            }
        }
    }
}

// ---------------- kernel 5: flash-MMA attention, 2 blocks/SM ---------------
// Key tile processed in two 64-key halves to halve P-fragment registers.
#define ATT_STAGE 42240
#define ATT_SMEM (20480 + 2 * ATT_STAGE)
__global__ void __launch_bounds__(256, 2) attn_mma() {
    extern __shared__ __align__(16) char asm_[];
    int qb = blockIdx.x, h = blockIdx.y, b = blockIdx.z;
    int m0 = qb * 128;
    int tid = threadIdx.x, w = tid >> 5, lane = tid & 31, g = lane >> 2, t = lane & 3;
    unsigned sb = smem_u32(asm_);
    const unsigned Qh = sb, Ql = sb + 10240;
    const float hs = 0.17677669529663687f;

    {
        const __nv_bfloat16* qh = g_qkh + ((size_t)b * NW + m0) * 768 + h * 96;
        const __nv_bfloat16* ql = g_qkl + ((size_t)b * NW + m0) * 768 + h * 96;
#pragma unroll
        for (int it = 0; it < 2; it++) {
            int idx = tid + it * 256;
            int row = idx >> 2, q = idx & 3;
            uint4 vh = *(const uint4*)(qh + (size_t)row * 768 + q * 8);
            uint4 vl = *(const uint4*)(ql + (size_t)row * 768 + q * 8);
            *(uint4*)(asm_ + row * 80 + q * 16) = vh;
            *(uint4*)(asm_ + 10240 + row * 80 + q * 16) = vl;
        }
    }
#pragma unroll
    for (int s = 0; s < 2; s++)
        for (int idx = tid; idx < 544; idx += 256) {
            int row = 32 + idx / 68, wd = idx % 68;
            ((unsigned*)(asm_ + 20480 + s * ATT_STAGE + 20480))[row * 68 + wd] =
                (row == 32 && wd < 64) ? 0x3F803F80u : 0u;
            ((unsigned*)(asm_ + 20480 + s * ATT_STAGE + 31360))[row * 68 + wd] = 0u;
        }
    __syncthreads();
    unsigned ah[2][4], al[2][4];
    {
        unsigned qa = Qh + (unsigned)(w * 16 + g) * 80 + t * 4;
        unsigned qa_l = Ql + (unsigned)(w * 16 + g) * 80 + t * 4;
#pragma unroll
        for (int kt2 = 0; kt2 < 2; kt2++) {
            unsigned o = kt2 * 32;
            ah[kt2][0] = lds32(qa + o);       ah[kt2][1] = lds32(qa + o + 640);
            ah[kt2][2] = lds32(qa + o + 16);  ah[kt2][3] = lds32(qa + o + 656);
            al[kt2][0] = lds32(qa_l + o);      al[kt2][1] = lds32(qa_l + o + 640);
            al[kt2][2] = lds32(qa_l + o + 16); al[kt2][3] = lds32(qa_l + o + 656);
        }
    }

    float O[5][4];
#pragma unroll
    for (int v = 0; v < 5; v++)
#pragma unroll
        for (int j = 0; j < 4; j++) O[v][j] = 0.f;

    int krow = tid >> 2, kq = tid & 3;
    const __nv_bfloat16* khb = g_qkh + (size_t)b * NW * 768 + h * 96 + 32;
    const __nv_bfloat16* klb = g_qkl + (size_t)b * NW * 768 + h * 96 + 32;
    int vd = tid >> 3, vseg = tid & 7;
    const unsigned short* vthb = g_vTh + (((size_t)b * 8 + h) * 32 + vd) * 1024 + vseg * 16;
    const unsigned short* vtlb = g_vTl + (((size_t)b * 8 + h) * 32 + vd) * 1024 + vseg * 16;

#define ATT_ISSUE(kt, s) do {                                                  \
    size_t nn = (size_t)(kt) * 128;                                            \
    unsigned ks_ = sb + 20480 + (s) * ATT_STAGE;                               \
    CPA16(ks_ + krow * 80 + kq * 16,               khb + (nn + krow) * 768 + kq * 8);      \
    CPA16(ks_ + 10240 + krow * 80 + kq * 16,       klb + (nn + krow) * 768 + kq * 8);      \
    CPA16(ks_ + (krow + 64) * 80 + kq * 16,        khb + (nn + krow + 64) * 768 + kq * 8); \
    CPA16(ks_ + 10240 + (krow + 64) * 80 + kq * 16, klb + (nn + krow + 64) * 768 + kq * 8);\
    CPA16(ks_ + 20480 + vd * 272 + vseg * 32,      vthb + nn);                 \
    CPA16(ks_ + 20480 + vd * 272 + vseg * 32 + 16, vthb + nn + 8);             \
    CPA16(ks_ + 31360 + vd * 272 + vseg * 32,      vtlb + nn);                 \
    CPA16(ks_ + 31360 + vd * 272 + vseg * 32 + 16, vtlb + nn + 8);             \
    CPA_COMMIT();                                                              \
} while (0)

    ATT_ISSUE(0, 0);
#pragma unroll 1
    for (int kt = 0; kt < 8; kt++) {
        if (kt < 7) { ATT_ISSUE(kt + 1, (kt + 1) & 1); CPA_WAIT(1); }
        else        { CPA_WAIT(0); }
        __syncthreads();
        unsigned ksb = sb + 20480 + (kt & 1) * ATT_STAGE;
        unsigned KhS = ksb, KlS = ksb + 10240, VhS = ksb + 20480, VlS = ksb + 31360;

#pragma unroll
        for (int half = 0; half < 2; half++) {
            unsigned pa_h[4][4], pa_l[4][4];
#pragma unroll
            for (int j = 0; j < 8; j++) {
                int jg = half * 8 + j;
                float s[4] = {0.f, 0.f, 0.f, 0.f};
                unsigned kbase = KhS + (unsigned)(jg * 8 + g) * 80 + t * 4;
                unsigned kbase_l = KlS + (unsigned)(jg * 8 + g) * 80 + t * 4;
#pragma unroll
                for (int kt2 = 0; kt2 < 2; kt2++) {
                    unsigned o = kt2 * 32;
                    unsigned bh[2] = {lds32(kbase + o), lds32(kbase + o + 16)};
                    unsigned bl[2] = {lds32(kbase_l + o), lds32(kbase_l + o + 16)};
                    mma16816(s, ah[kt2], bh);
                    mma16816(s, ah[kt2], bl);
                    mma16816(s, al[kt2], bh);
                }
                float p0 = __expf(s[0] * hs), p1 = __expf(s[1] * hs);
                float p2 = __expf(s[2] * hs), p3 = __expf(s[3] * hs);
                unsigned h01 = pack_bf16x2(p0, p1);
                unsigned h23 = pack_bf16x2(p2, p3);
                unsigned l01 = pack_bf16x2(p0 - __uint_as_float(h01 << 16),
                                           p1 - __uint_as_float(h01 & 0xffff0000u));
                unsigned l23 = pack_bf16x2(p2 - __uint_as_float(h23 << 16),
                                           p3 - __uint_as_float(h23 & 0xffff0000u));
                int kk = j >> 1, hf = (j & 1) * 2;
                pa_h[kk][hf] = h01; pa_h[kk][hf + 1] = h23;
                pa_l[kk][hf] = l01; pa_l[kk][hf + 1] = l23;
            }
#pragma unroll
            for (int v = 0; v < 5; v++) {
                unsigned vb = VhS + (unsigned)(v * 8 + g) * 272 + t * 4;
                unsigned vb_l = VlS + (unsigned)(v * 8 + g) * 272 + t * 4;
#pragma unroll
                for (int kk = 0; kk < 4; kk++) {
                    unsigned o = (half * 4 + kk) * 32;
                    unsigned bh[2] = {lds32(vb + o), lds32(vb + o + 16)};
                    unsigned bl[2] = {lds32(vb_l + o), lds32(vb_l + o + 16)};
                    mma16816(O[v], pa_h[kk], bh);
                    mma16816(O[v], pa_h[kk], bl);
                    mma16816(O[v], pa_l[kk], bh);
                }
            }
        }
        __syncthreads();
    }
#undef ATT_ISSUE
    float lg = __shfl_sync(0xffffffffu, O[4][0], lane & 28);
    float lg8 = __shfl_sync(0xffffffffu, O[4][2], lane & 28);
    float inv = 1.f / lg, inv8 = 1.f / lg8;
    size_t ob = ((size_t)b * NW + m0 + w * 16 + g) * 256 + h * 32;
    size_t ob8 = ob + (size_t)8 * 256;
#pragma unroll
    for (int v = 0; v < 4; v++) {
        int d = v * 8 + t * 2;
        float x0 = O[v][0] * inv, x1 = O[v][1] * inv;
        float x2 = O[v][2] * inv8, x3 = O[v][3] * inv8;
        unsigned hp0 = pack_bf16x2(x0, x1);
        unsigned lp0 = pack_bf16x2(x0 - __uint_as_float(hp0 << 16),
                                   x1 - __uint_as_float(hp0 & 0xffff0000u));
        unsigned hp1 = pack_bf16x2(x2, x3);
        unsigned lp1 = pack_bf16x2(x2 - __uint_as_float(hp1 << 16),
                                   x3 - __uint_as_float(hp1 & 0xffff0000u));
        *(unsigned*)&g_aoh[ob + d] = hp0;
        *(unsigned*)&g_aol[ob + d] = lp0;
        *(unsigned*)&g_aoh[ob8 + d] = hp1;
        *(unsigned*)&g_aol[ob8 + d] = lp1;
    }
}

// ---------------- kernel 7: scatter, c-split across blockIdx.z --------------
__global__ void scatter_kernel(float* __restrict__ out) {
    __shared__ float aff_s[32 * 144];
    __shared__ float r_s[3 * 34 * 33];
    int Y = blockIdx.x, b = blockIdx.y;
    int cbase = blockIdx.z * 64;      // 64-channel slice per block
    int tid = threadIdx.x;
    int X = tid >> 2, px = tid & 3;
    const float* ab = g_aff + ((size_t)b * NW + Y * 32) * 144;
    for (int idx = tid; idx < 4608; idx += 128) aff_s[idx] = ab[idx];
    for (int idx = tid; idx < 3 * 34 * 33; idx += 128) r_s[idx] = 0.f;
    __syncthreads();
    float a[4][9];
#pragma unroll
    for (int py = 0; py < 4; py++)
#pragma unroll
        for (int i = 0; i < 9; i++)
            a[py][i] = aff_s[X * 144 + (py * 4 + px) * 9 + i];

#pragma unroll
    for (int cc0 = 0; cc0 < 64; cc0 += 32) {
        int c0 = cbase + cc0;
        __syncthreads();
        for (int idx = tid; idx < 3 * 32 * 32; idx += 128) {
            int dy = idx >> 10;
            int rem = idx & 1023;
            int Xl = rem >> 5, cc = rem & 31;
            int ny = Y + dy - 1;
            if ((unsigned)ny < 32u)
                r_s[((dy * 34) + Xl + 1) * 33 + cc] =
                    g_proj[((size_t)b * NW + ny * 32 + Xl) * Cv + c0 + cc];
        }
        __syncthreads();
#pragma unroll 4
        for (int c = 0; c < 32; c++) {
            float r[9];
#pragma unroll
            for (int i = 0; i < 9; i++) {
                int dy = i / 3, dx = i % 3;
                r[i] = r_s[((dy * 34) + X + dx) * 33 + c];
            }
            size_t obase = ((size_t)b * 256 + c0 + c) * 16384 +
                           (size_t)(Y * 4) * 128 + tid;
#pragma unroll
            for (int py = 0; py < 4; py++) {
                float v = 0.f;
#pragma unroll
                for (int i = 0; i < 9; i++) v = fmaf(r[i], a[py][i], v);
                out[obase + (size_t)py * 128] = v;
            }
        }
    }
}

// ---------------- launch ----------------
extern "C" void kernel_launch(void* const* d_in, const int* in_sizes, int n_in,
                              void* d_out, int out_size) {
    const float* x = nullptr; const float* qkv_w = nullptr;
    const float* proj_w = nullptr; const float* proj_b = nullptr;
    for (int i = 0; i < n_in; i++) {
        int s = in_sizes[i];
        if (s == 8 * 16384 * 256) x = (const float*)d_in[i];
        else if (s == 768 * 256)  qkv_w = (const float*)d_in[i];
        else if (s == 256 * 256)  proj_w = (const float*)d_in[i];
        else if (s == 256)        proj_b = (const float*)d_in[i];
    }
    float* out = (float*)d_out;

    const int DSMEM = 2 * STG_STRIDE;
    cudaFuncSetAttribute(gemm_mma, cudaFuncAttributeMaxDynamicSharedMemorySize, DSMEM);
    cudaFuncSetAttribute(attn_mma, cudaFuncAttributeMaxDynamicSharedMemorySize, ATT_SMEM);

    pool_kernel<<<dim3(256, 8), 256>>>(x);
    conv_w<<<768, 256>>>(qkv_w, proj_w);
    aff_kernel<<<dim3(1024, 8), 256>>>(x);
    fold_kernel<<<dim3(256, 8), 256>>>();
    gemm_mma<<<dim3(8, 6, 8), 256, DSMEM>>>(0, nullptr, 768);
    attn_mma<<<dim3(8, 8, 8), 256, ATT_SMEM>>>();
    gemm_mma<<<dim3(8, 2, 8), 256, DSMEM>>>(1, proj_b, 256);
    scatter_kernel<<<dim3(32, 8, 4), 128>>>(out);
}